// round 1
// baseline (speedup 1.0000x reference)
#include <cuda_runtime.h>
#include <math.h>

// Problem constants (fixed by the reference)
#define TT   2048   // tokens
#define NH   16     // query heads
#define DD   64     // head dim
#define NBS  64     // block size
#define NS   16     // selected blocks per token

__global__ void __launch_bounds__(256) nsa_kernel(
    const float* __restrict__ Q,   // [T, H, D]
    const float* __restrict__ K,   // [T, 1, D] -> [NB, BS, D]
    const float* __restrict__ V,   // [T, 1, D]
    const int*   __restrict__ BI,  // [T, 1, S]
    float* __restrict__ Out)       // [T, H, D]
{
    __shared__ float Qs[NH * DD];    // [h][d], pre-scaled by 1/sqrt(D)
    __shared__ float Kt[DD * NBS];   // [d][k]  (transposed -> conflict-free QK)
    __shared__ float Vs[NBS * DD];   // [k][d]  (row-major  -> conflict-free PV)
    __shared__ float Ps[NH * NBS];   // [h][k]  per-warp-private rows

    const int t    = blockIdx.x;
    const int tid  = threadIdx.x;
    const int lane = tid & 31;
    const int warp = tid >> 5;
    const int h0   = warp * 2;
    const int h1   = h0 + 1;
    const int krow = tid & 63;   // K-load: row within block
    const int kdc  = tid >> 6;   // K-load: dchunk group 0..3

    // Load Q for this token, fold in softmax scale. 256 float4 = 16*64 floats.
    {
        const float SCALE = 0.125f; // 1/sqrt(64)
        float4 q = ((const float4*)(Q + t * NH * DD))[tid];
        q.x *= SCALE; q.y *= SCALE; q.z *= SCALE; q.w *= SCALE;
        ((float4*)Qs)[tid] = q;
    }

    // Online-softmax state, 2 heads per warp, lane owns d=lane and d=lane+32.
    float m0 = -INFINITY, l0 = 0.f, o00 = 0.f, o01 = 0.f;
    float m1 = -INFINITY, l1 = 0.f, o10 = 0.f, o11 = 0.f;

    for (int s = 0; s < NS; ++s) {
        const int blk = BI[t * NS + s];
        const float* Kg = K + blk * NBS * DD;
        const float* Vg = V + blk * NBS * DD;

        __syncthreads();  // previous block's compute done before overwrite

        // Load K transposed: Kt[d][row]. Lanes vary row -> conflict-free STS.
        #pragma unroll
        for (int it = 0; it < 4; ++it) {
            const int dch = kdc + it * 4;         // 0..15
            float4 kv = *(const float4*)(Kg + krow * DD + dch * 4);
            Kt[(dch * 4 + 0) * NBS + krow] = kv.x;
            Kt[(dch * 4 + 1) * NBS + krow] = kv.y;
            Kt[(dch * 4 + 2) * NBS + krow] = kv.z;
            Kt[(dch * 4 + 3) * NBS + krow] = kv.w;
        }
        // Load V row-major, fully coalesced float4.
        #pragma unroll
        for (int it = 0; it < 4; ++it)
            ((float4*)Vs)[tid + it * 256] = ((const float4*)Vg)[tid + it * 256];

        __syncthreads();

        // --- QK: lane computes keys k=lane and k=lane+32 for heads h0,h1 ---
        float s00 = 0.f, s01 = 0.f, s10 = 0.f, s11 = 0.f;
        #pragma unroll
        for (int d = 0; d < DD; ++d) {
            const float k0 = Kt[d * NBS + lane];
            const float k1 = Kt[d * NBS + lane + 32];
            const float q0 = Qs[h0 * DD + d];   // broadcast
            const float q1 = Qs[h1 * DD + d];   // broadcast
            s00 += q0 * k0; s01 += q0 * k1;
            s10 += q1 * k0; s11 += q1 * k1;
        }

        // Causal mask on absolute key positions.
        const int kp0 = blk * NBS + lane;
        const int kp1 = kp0 + 32;
        if (kp0 > t) { s00 = -INFINITY; s10 = -INFINITY; }
        if (kp1 > t) { s01 = -INFINITY; s11 = -INFINITY; }

        // --- online softmax update, head 0 ---
        {
            float bm = fmaxf(s00, s01);
            #pragma unroll
            for (int off = 16; off; off >>= 1)
                bm = fmaxf(bm, __shfl_xor_sync(0xffffffffu, bm, off));
            const float mn = fmaxf(m0, bm);
            float e0 = 0.f, e1 = 0.f;
            if (mn > -INFINITY) {   // guard: fully-masked block contributes nothing
                e0 = __expf(s00 - mn);
                e1 = __expf(s01 - mn);
                const float corr = __expf(m0 - mn);
                float ps = e0 + e1;
                #pragma unroll
                for (int off = 16; off; off >>= 1)
                    ps += __shfl_xor_sync(0xffffffffu, ps, off);
                l0 = l0 * corr + ps;
                o00 *= corr; o01 *= corr;
                m0 = mn;
            }
            Ps[h0 * NBS + lane]      = e0;
            Ps[h0 * NBS + lane + 32] = e1;
        }
        // --- online softmax update, head 1 ---
        {
            float bm = fmaxf(s10, s11);
            #pragma unroll
            for (int off = 16; off; off >>= 1)
                bm = fmaxf(bm, __shfl_xor_sync(0xffffffffu, bm, off));
            const float mn = fmaxf(m1, bm);
            float e0 = 0.f, e1 = 0.f;
            if (mn > -INFINITY) {
                e0 = __expf(s10 - mn);
                e1 = __expf(s11 - mn);
                const float corr = __expf(m1 - mn);
                float ps = e0 + e1;
                #pragma unroll
                for (int off = 16; off; off >>= 1)
                    ps += __shfl_xor_sync(0xffffffffu, ps, off);
                l1 = l1 * corr + ps;
                o10 *= corr; o11 *= corr;
                m1 = mn;
            }
            Ps[h1 * NBS + lane]      = e0;
            Ps[h1 * NBS + lane + 32] = e1;
        }
        __syncwarp();   // Ps rows are warp-private; order STS -> LDS

        // --- PV: lane owns d=lane and d=lane+32 for heads h0,h1 ---
        #pragma unroll
        for (int k = 0; k < NBS; ++k) {
            const float p0 = Ps[h0 * NBS + k];          // broadcast
            const float p1 = Ps[h1 * NBS + k];          // broadcast
            const float v0 = Vs[k * DD + lane];
            const float v1 = Vs[k * DD + lane + 32];
            o00 += p0 * v0; o01 += p0 * v1;
            o10 += p1 * v0; o11 += p1 * v1;
        }
        __syncwarp();   // WAR: next iteration overwrites Ps
    }

    // Normalize and write out. At least one valid key guaranteed => l > 0.
    const float inv0 = 1.0f / l0;
    const float inv1 = 1.0f / l1;
    float* op = Out + t * NH * DD;
    op[h0 * DD + lane]      = o00 * inv0;
    op[h0 * DD + lane + 32] = o01 * inv0;
    op[h1 * DD + lane]      = o10 * inv1;
    op[h1 * DD + lane + 32] = o11 * inv1;
}

extern "C" void kernel_launch(void* const* d_in, const int* in_sizes, int n_in,
                              void* d_out, int out_size) {
    const float* Q  = (const float*)d_in[0];
    const float* K  = (const float*)d_in[1];
    const float* V  = (const float*)d_in[2];
    const int*   BI = (const int*)d_in[3];
    float* Out = (float*)d_out;

    nsa_kernel<<<TT, 256>>>(Q, K, V, BI, Out);
}

// round 2
// speedup vs baseline: 1.1499x; 1.1499x over previous
#include <cuda_runtime.h>
#include <math.h>

#define TT   2048
#define NHD  16
#define DDIM 64
#define BSZ  64
#define NSEL 16

// ---- tf32 helpers ----------------------------------------------------------
__device__ __forceinline__ unsigned f2tf(float x) {
    unsigned r; asm("cvt.rna.tf32.f32 %0, %1;" : "=r"(r) : "f"(x)); return r;
}
__device__ __forceinline__ void split_tf(float x, unsigned &hi, unsigned &lo) {
    hi = f2tf(x);
    lo = f2tf(x - __uint_as_float(hi));
}
__device__ __forceinline__ void mma8(float c[4], const unsigned a[4],
                                     unsigned b0, unsigned b1) {
    asm volatile(
        "mma.sync.aligned.m16n8k8.row.col.f32.tf32.tf32.f32 "
        "{%0,%1,%2,%3}, {%4,%5,%6,%7}, {%8,%9}, {%0,%1,%2,%3};\n"
        : "+f"(c[0]), "+f"(c[1]), "+f"(c[2]), "+f"(c[3])
        : "r"(a[0]), "r"(a[1]), "r"(a[2]), "r"(a[3]), "r"(b0), "r"(b1));
}

// ---- kernel ----------------------------------------------------------------
// One CTA per query token. 8 warps.
// QK:  warp w computes scores for keys [8w, 8w+8)  (n-tile split).
// PV:  warp w accumulates O-partial over the SAME keys (k split), all 64 d.
// Softmax max is exchanged CTA-wide; all warps track identical m, so the
// final merge is a plain sum of l and of O partials.
__global__ void __launch_bounds__(256, 2) nsa_mma(
    const float* __restrict__ Q,   // [T, 16, 64]
    const float* __restrict__ K,   // [T, 1, 64] == [32 blocks][64][64]
    const float* __restrict__ V,
    const int*   __restrict__ BI,  // [T, 1, 16]
    float* __restrict__ Out)       // [T, 16, 64]
{
    __shared__ float Ks[64 * 68];    // K tile, row stride 68 (CF for QK B-frags)
    __shared__ float Vs[64 * 72];    // V tile, row stride 72 (CF for PV B-frags)
    __shared__ float Qs[16 * 68];    // Q staging
    __shared__ float Pw[8 * 192];    // per-warp P buffer, 16 rows x stride 12
    __shared__ float pmax[8][16];    // per-warp per-head partial max
    __shared__ float lsum[8][16];    // per-warp per-head partial l

    const int t    = blockIdx.x;
    const int tid  = threadIdx.x;
    const int w    = tid >> 5;
    const int lane = tid & 31;
    const int gid  = lane >> 2;      // 0..7  (row group)
    const int qid  = lane & 3;       // 0..3  (thread-in-group)

    // ---- stage Q (scaled by 1/sqrt(64)) -----------------------------------
    {
        float4 qv = ((const float4*)(Q + t * 1024))[tid];
        qv.x *= 0.125f; qv.y *= 0.125f; qv.z *= 0.125f; qv.w *= 0.125f;
        const int row = tid >> 4, c4 = tid & 15;
        *(float4*)(Qs + row * 68 + c4 * 4) = qv;
    }
    __syncthreads();

    // ---- Q A-fragments (fp32 in regs; split to tf32 hi/lo per use) --------
    float qf[8][4];
    #pragma unroll
    for (int ks = 0; ks < 8; ++ks) {
        qf[ks][0] = Qs[ gid      * 68 + 8 * ks + qid    ];
        qf[ks][1] = Qs[(gid + 8) * 68 + 8 * ks + qid    ];
        qf[ks][2] = Qs[ gid      * 68 + 8 * ks + qid + 4];
        qf[ks][3] = Qs[(gid + 8) * 68 + 8 * ks + qid + 4];
    }

    float o[8][4];
    #pragma unroll
    for (int nt = 0; nt < 8; ++nt)
        o[nt][0] = o[nt][1] = o[nt][2] = o[nt][3] = 0.f;
    float m0 = -INFINITY, m1 = -INFINITY, l0 = 0.f, l1 = 0.f;

    for (int s = 0; s < NSEL; ++s) {
        const int blk = BI[t * NSEL + s];
        __syncthreads();   // previous block's fragment reads complete

        // ---- stage K, V tiles (64x64 fp32 each) ---------------------------
        {
            const float4* Kb = (const float4*)(K + blk * 64 * 64);
            const float4* Vb = (const float4*)(V + blk * 64 * 64);
            #pragma unroll
            for (int j = 0; j < 4; ++j) {
                const int i = tid + j * 256;
                const int row = i >> 4, c4 = i & 15;
                *(float4*)(Ks + row * 68 + c4 * 4) = Kb[i];
                *(float4*)(Vs + row * 72 + c4 * 4) = Vb[i];
            }
        }
        __syncthreads();

        // ---- QK: warp's n-tile = keys [8w, 8w+8), 3xTF32 ------------------
        float sc[4] = {0.f, 0.f, 0.f, 0.f};
        #pragma unroll
        for (int ks = 0; ks < 8; ++ks) {
            const float b0 = Ks[(8 * w + gid) * 68 + 8 * ks + qid    ];
            const float b1 = Ks[(8 * w + gid) * 68 + 8 * ks + qid + 4];
            unsigned b0h, b0l, b1h, b1l;
            split_tf(b0, b0h, b0l);
            split_tf(b1, b1h, b1l);
            unsigned ah[4], al[4];
            #pragma unroll
            for (int i = 0; i < 4; ++i) split_tf(qf[ks][i], ah[i], al[i]);
            mma8(sc, ah, b0h, b1h);
            mma8(sc, al, b0h, b1h);
            mma8(sc, ah, b0l, b1l);
        }

        // ---- causal mask (absolute key positions) -------------------------
        {
            const int kp = blk * 64 + 8 * w + 2 * qid;   // col of sc[0]/sc[2]
            if (kp     > t) { sc[0] = -INFINITY; sc[2] = -INFINITY; }
            if (kp + 1 > t) { sc[1] = -INFINITY; sc[3] = -INFINITY; }
        }

        // ---- per-warp row max over its 8 keys -----------------------------
        float r0 = fmaxf(sc[0], sc[1]);
        r0 = fmaxf(r0, __shfl_xor_sync(0xffffffffu, r0, 1));
        r0 = fmaxf(r0, __shfl_xor_sync(0xffffffffu, r0, 2));
        float r1 = fmaxf(sc[2], sc[3]);
        r1 = fmaxf(r1, __shfl_xor_sync(0xffffffffu, r1, 1));
        r1 = fmaxf(r1, __shfl_xor_sync(0xffffffffu, r1, 2));
        if (qid == 0) { pmax[w][gid] = r0; pmax[w][gid + 8] = r1; }
        __syncthreads();

        // ---- CTA-wide running max (identical in every warp) ---------------
        float bm0 = m0, bm1 = m1;
        #pragma unroll
        for (int ww = 0; ww < 8; ++ww) {
            bm0 = fmaxf(bm0, pmax[ww][gid]);
            bm1 = fmaxf(bm1, pmax[ww][gid + 8]);
        }
        const float s0 = (bm0 == -INFINITY) ? 0.f : bm0;  // NaN-safe subtrahend
        const float s1 = (bm1 == -INFINITY) ? 0.f : bm1;
        const float corr0 = __expf(m0 - s0);   // m=-inf -> 0
        const float corr1 = __expf(m1 - s1);

        const float p0 = __expf(sc[0] - s0);
        const float p1 = __expf(sc[1] - s0);
        const float p2 = __expf(sc[2] - s1);
        const float p3 = __expf(sc[3] - s1);

        float pl0 = p0 + p1;
        pl0 += __shfl_xor_sync(0xffffffffu, pl0, 1);
        pl0 += __shfl_xor_sync(0xffffffffu, pl0, 2);
        float pl1 = p2 + p3;
        pl1 += __shfl_xor_sync(0xffffffffu, pl1, 1);
        pl1 += __shfl_xor_sync(0xffffffffu, pl1, 2);
        l0 = l0 * corr0 + pl0;
        l1 = l1 * corr1 + pl1;
        m0 = bm0; m1 = bm1;

        #pragma unroll
        for (int nt = 0; nt < 8; ++nt) {
            o[nt][0] *= corr0; o[nt][1] *= corr0;
            o[nt][2] *= corr1; o[nt][3] *= corr1;
        }

        // ---- C-layout -> A-layout via tiny per-warp SMEM buffer -----------
        float* pb = Pw + w * 192;
        pb[ gid      * 12 + 2 * qid    ] = p0;
        pb[ gid      * 12 + 2 * qid + 1] = p1;
        pb[(gid + 8) * 12 + 2 * qid    ] = p2;
        pb[(gid + 8) * 12 + 2 * qid + 1] = p3;
        __syncwarp();
        float pa[4];
        pa[0] = pb[ gid      * 12 + qid    ];
        pa[1] = pb[(gid + 8) * 12 + qid    ];
        pa[2] = pb[ gid      * 12 + qid + 4];
        pa[3] = pb[(gid + 8) * 12 + qid + 4];
        unsigned pah[4], pal[4];
        #pragma unroll
        for (int i = 0; i < 4; ++i) split_tf(pa[i], pah[i], pal[i]);

        // ---- PV: warp's keys as the single k-step, all 8 d-tiles ----------
        #pragma unroll
        for (int nt = 0; nt < 8; ++nt) {
            const float v0 = Vs[(8 * w + qid    ) * 72 + 8 * nt + gid];
            const float v1 = Vs[(8 * w + qid + 4) * 72 + 8 * nt + gid];
            unsigned v0h, v0l, v1h, v1l;
            split_tf(v0, v0h, v0l);
            split_tf(v1, v1h, v1l);
            mma8(o[nt], pah, v0h, v1h);
            mma8(o[nt], pal, v0h, v1h);
            mma8(o[nt], pah, v0l, v1l);
        }
    }

    // ---- merge: sum l across warps, then sum O partials via output --------
    if (qid == 0) { lsum[w][gid] = l0; lsum[w][gid + 8] = l1; }
    __syncthreads();
    float lt0 = 0.f, lt1 = 0.f;
    #pragma unroll
    for (int ww = 0; ww < 8; ++ww) {
        lt0 += lsum[ww][gid];
        lt1 += lsum[ww][gid + 8];
    }
    const float inv0 = 1.f / lt0;
    const float inv1 = 1.f / lt1;

    // O partials: reduce across warps through SMEM (reuse Ks as scratch).
    // Each warp writes its scaled partial into its own region, then all sum.
    float* buf = Ks + w * 16 * 68;     // 16x68 per warp region fits in Ks? 8*1088=8704<4352? NO.
    // Ks holds 4352 floats; need 8*1088 = 8704. Use Ks+Vs contiguous? Not
    // guaranteed contiguous. Instead: tree-free accumulation via Vs+Ks split:
    // warps 0-3 use Ks (4*1088=4352 exact), warps 4-7 use Vs (within 4608).
    float* reg = (w < 4) ? (Ks + w * 1088) : (Vs + (w - 4) * 1088);
    #pragma unroll
    for (int nt = 0; nt < 8; ++nt) {
        reg[ gid      * 68 + 8 * nt + 2 * qid    ] = o[nt][0];
        reg[ gid      * 68 + 8 * nt + 2 * qid + 1] = o[nt][1];
        reg[(gid + 8) * 68 + 8 * nt + 2 * qid    ] = o[nt][2];
        reg[(gid + 8) * 68 + 8 * nt + 2 * qid + 1] = o[nt][3];
    }
    __syncthreads();

    // 1024 outputs, 256 threads x 4 elems, coalesced.
    float* ob = Out + t * 1024;
    #pragma unroll
    for (int i = 0; i < 4; ++i) {
        const int e = tid + i * 256;
        const int h = e >> 6, d = e & 63;
        float acc = 0.f;
        #pragma unroll
        for (int ww = 0; ww < 4; ++ww) {
            acc += Ks[ww * 1088 + h * 68 + d];
            acc += Vs[ww * 1088 + h * 68 + d];
        }
        // per-head normalizer
        float lt = 0.f;
        #pragma unroll
        for (int ww = 0; ww < 8; ++ww) lt += lsum[ww][h];
        ob[e] = acc / lt;
    }
    (void)inv0; (void)inv1;
}

extern "C" void kernel_launch(void* const* d_in, const int* in_sizes, int n_in,
                              void* d_out, int out_size) {
    const float* Q  = (const float*)d_in[0];
    const float* K  = (const float*)d_in[1];
    const float* V  = (const float*)d_in[2];
    const int*   BI = (const int*)d_in[3];
    nsa_mma<<<TT, 256>>>(Q, K, V, BI, (float*)d_out);
}

// round 3
// speedup vs baseline: 1.7779x; 1.5461x over previous
#include <cuda_runtime.h>
#include <cuda_bf16.h>
#include <math.h>

#define TT 2048

// Scratch: bf16 hi/lo splits of K and V (V pre-transposed per 64-block).
__device__ __nv_bfloat16 g_Khi[131072];   // [2048 tok][64 d]
__device__ __nv_bfloat16 g_Klo[131072];
__device__ __nv_bfloat16 g_Vthi[131072];  // [32 blk][64 d][64 key]
__device__ __nv_bfloat16 g_Vtlo[131072];

__global__ void __launch_bounds__(256) split_kernel(
    const float* __restrict__ K, const float* __restrict__ V)
{
    const int i = blockIdx.x * 256 + threadIdx.x;   // 0..131071
    // K: same layout
    {
        float k = K[i];
        __nv_bfloat16 kh = __float2bfloat16(k);
        g_Khi[i] = kh;
        g_Klo[i] = __float2bfloat16(k - __bfloat162float(kh));
    }
    // V transposed: i -> (blk, d, key); read V[(blk*64+key)*64 + d]
    {
        const int blk = i >> 12;
        const int d   = (i >> 6) & 63;
        const int kk  = i & 63;
        float v = V[(blk * 64 + kk) * 64 + d];
        __nv_bfloat16 vh = __float2bfloat16(v);
        g_Vthi[i] = vh;
        g_Vtlo[i] = __float2bfloat16(v - __bfloat162float(vh));
    }
}

__device__ __forceinline__ void mma16(float c[4], const unsigned a[4],
                                      unsigned b0, unsigned b1) {
    asm volatile(
        "mma.sync.aligned.m16n8k16.row.col.f32.bf16.bf16.f32 "
        "{%0,%1,%2,%3}, {%4,%5,%6,%7}, {%8,%9}, {%0,%1,%2,%3};\n"
        : "+f"(c[0]), "+f"(c[1]), "+f"(c[2]), "+f"(c[3])
        : "r"(a[0]), "r"(a[1]), "r"(a[2]), "r"(a[3]), "r"(b0), "r"(b1));
}

// One CTA per token, 8 warps.
// QK: warp w -> keys [8w,8w+8) (n-split).  PV: warp w -> dims [8w,8w+8) (d-split),
// P exchanged CTA-wide through SMEM. All in bf16 hi/lo 3-term emulation.
__global__ void __launch_bounds__(256, 3) nsa_bf16(
    const float* __restrict__ Q,   // [T,16,64]
    const int*   __restrict__ BI,  // [T,16]
    float* __restrict__ Out)       // [T,16,64]
{
    __shared__ __nv_bfloat16 Ksh[64 * 72];   // K hi, [key][d] stride 72
    __shared__ __nv_bfloat16 Ksl[64 * 72];
    __shared__ __nv_bfloat16 Vth[64 * 72];   // Vt hi, [d][key] stride 72
    __shared__ __nv_bfloat16 Vtl[64 * 72];
    __shared__ __nv_bfloat16 Ph[16 * 72];    // P hi, [head][key] stride 72
    __shared__ __nv_bfloat16 Pl[16 * 72];
    __shared__ float pmax[8][16];
    __shared__ float lsum[8][16];

    const int t    = blockIdx.x;
    const int tid  = threadIdx.x;
    const int w    = tid >> 5;
    const int lane = tid & 31;
    const int gid  = lane >> 2;   // 0..7
    const int qid  = lane & 3;    // 0..3

    // ---- Q A-fragments: load from global, scale, split to bf16 hi/lo ------
    unsigned qh[4][4], ql[4][4];
    {
        const float* Qp = Q + t * 1024;
        #pragma unroll
        for (int ks = 0; ks < 4; ++ks) {
            #pragma unroll
            for (int j = 0; j < 4; ++j) {
                const int row = (j & 1) ? gid + 8 : gid;
                const int col = 16 * ks + 2 * qid + ((j >> 1) ? 8 : 0);
                float2 x = *(const float2*)(Qp + row * 64 + col);
                x.x *= 0.125f; x.y *= 0.125f;
                __nv_bfloat162 h = __float22bfloat162_rn(x);
                float2 r = make_float2(x.x - __low2float(h),
                                       x.y - __high2float(h));
                __nv_bfloat162 l = __float22bfloat162_rn(r);
                qh[ks][j] = *(unsigned*)&h;
                ql[ks][j] = *(unsigned*)&l;
            }
        }
    }

    float o[4] = {0.f, 0.f, 0.f, 0.f};
    float m0 = -INFINITY, m1 = -INFINITY, l0 = 0.f, l1 = 0.f;

    for (int s = 0; s < 16; ++s) {
        const int blk = BI[t * 16 + s];
        __syncthreads();   // prior iter's SMEM reads complete

        // ---- stage: straight 16B copies, bf16, padded rows -----------------
        {
            const int4* Ks_g = (const int4*)(g_Khi + blk * 4096);
            const int4* Kl_g = (const int4*)(g_Klo + blk * 4096);
            const int4* Vh_g = (const int4*)(g_Vthi + blk * 4096);
            const int4* Vl_g = (const int4*)(g_Vtlo + blk * 4096);
            #pragma unroll
            for (int j = 0; j < 2; ++j) {
                const int idx = tid + j * 256;      // chunk 0..511
                const int row = idx >> 3, c = idx & 7;
                const int dst = row * 72 + c * 8;
                *(int4*)(Ksh + dst) = Ks_g[idx];
                *(int4*)(Ksl + dst) = Kl_g[idx];
                *(int4*)(Vth + dst) = Vh_g[idx];
                *(int4*)(Vtl + dst) = Vl_g[idx];
            }
        }
        __syncthreads();

        // ---- QK: scores for 16 heads x warp's 8 keys ----------------------
        float sc[4] = {0.f, 0.f, 0.f, 0.f};
        #pragma unroll
        for (int ks = 0; ks < 4; ++ks) {
            const __nv_bfloat16* kb = Ksh + (8 * w + gid) * 72 + 16 * ks + 2 * qid;
            const __nv_bfloat16* kl = Ksl + (8 * w + gid) * 72 + 16 * ks + 2 * qid;
            const unsigned bh0 = *(const unsigned*)kb;
            const unsigned bh1 = *(const unsigned*)(kb + 8);
            const unsigned bl0 = *(const unsigned*)kl;
            const unsigned bl1 = *(const unsigned*)(kl + 8);
            mma16(sc, qh[ks], bh0, bh1);
            mma16(sc, ql[ks], bh0, bh1);
            mma16(sc, qh[ks], bl0, bl1);
        }

        // ---- causal mask --------------------------------------------------
        {
            const int kp = blk * 64 + 8 * w + 2 * qid;
            if (kp     > t) { sc[0] = -INFINITY; sc[2] = -INFINITY; }
            if (kp + 1 > t) { sc[1] = -INFINITY; sc[3] = -INFINITY; }
        }

        // ---- per-warp row max, exchange CTA-wide --------------------------
        float r0 = fmaxf(sc[0], sc[1]);
        r0 = fmaxf(r0, __shfl_xor_sync(0xffffffffu, r0, 1));
        r0 = fmaxf(r0, __shfl_xor_sync(0xffffffffu, r0, 2));
        float r1 = fmaxf(sc[2], sc[3]);
        r1 = fmaxf(r1, __shfl_xor_sync(0xffffffffu, r1, 1));
        r1 = fmaxf(r1, __shfl_xor_sync(0xffffffffu, r1, 2));
        if (qid == 0) { pmax[w][gid] = r0; pmax[w][gid + 8] = r1; }
        __syncthreads();

        float bm0 = m0, bm1 = m1;
        #pragma unroll
        for (int ww = 0; ww < 8; ++ww) {
            bm0 = fmaxf(bm0, pmax[ww][gid]);
            bm1 = fmaxf(bm1, pmax[ww][gid + 8]);
        }
        const float s0 = (bm0 == -INFINITY) ? 0.f : bm0;
        const float s1 = (bm1 == -INFINITY) ? 0.f : bm1;
        const float corr0 = __expf(m0 - s0);
        const float corr1 = __expf(m1 - s1);

        const float p0 = __expf(sc[0] - s0);
        const float p1 = __expf(sc[1] - s0);
        const float p2 = __expf(sc[2] - s1);
        const float p3 = __expf(sc[3] - s1);

        float pl0 = p0 + p1;
        pl0 += __shfl_xor_sync(0xffffffffu, pl0, 1);
        pl0 += __shfl_xor_sync(0xffffffffu, pl0, 2);
        float pl1 = p2 + p3;
        pl1 += __shfl_xor_sync(0xffffffffu, pl1, 1);
        pl1 += __shfl_xor_sync(0xffffffffu, pl1, 2);
        l0 = l0 * corr0 + pl0;
        l1 = l1 * corr1 + pl1;
        m0 = bm0; m1 = bm1;

        // rescale O (rows gid -> corr0, rows gid+8 -> corr1)
        o[0] *= corr0; o[1] *= corr0; o[2] *= corr1; o[3] *= corr1;

        // ---- publish P as bf16 hi/lo pairs --------------------------------
        {
            __nv_bfloat162 h01 = __float22bfloat162_rn(make_float2(p0, p1));
            __nv_bfloat162 l01 = __float22bfloat162_rn(
                make_float2(p0 - __low2float(h01), p1 - __high2float(h01)));
            __nv_bfloat162 h23 = __float22bfloat162_rn(make_float2(p2, p3));
            __nv_bfloat162 l23 = __float22bfloat162_rn(
                make_float2(p2 - __low2float(h23), p3 - __high2float(h23)));
            const int c = 8 * w + 2 * qid;
            *(__nv_bfloat162*)(Ph + gid * 72 + c)       = h01;
            *(__nv_bfloat162*)(Pl + gid * 72 + c)       = l01;
            *(__nv_bfloat162*)(Ph + (gid + 8) * 72 + c) = h23;
            *(__nv_bfloat162*)(Pl + (gid + 8) * 72 + c) = l23;
        }
        __syncthreads();

        // ---- PV: warp's 8 dims, k over all 64 keys ------------------------
        #pragma unroll
        for (int ks = 0; ks < 4; ++ks) {
            unsigned ah[4], al[4];
            const int c0 = 16 * ks + 2 * qid;
            ah[0] = *(const unsigned*)(Ph + gid * 72 + c0);
            ah[1] = *(const unsigned*)(Ph + (gid + 8) * 72 + c0);
            ah[2] = *(const unsigned*)(Ph + gid * 72 + c0 + 8);
            ah[3] = *(const unsigned*)(Ph + (gid + 8) * 72 + c0 + 8);
            al[0] = *(const unsigned*)(Pl + gid * 72 + c0);
            al[1] = *(const unsigned*)(Pl + (gid + 8) * 72 + c0);
            al[2] = *(const unsigned*)(Pl + gid * 72 + c0 + 8);
            al[3] = *(const unsigned*)(Pl + (gid + 8) * 72 + c0 + 8);

            const __nv_bfloat16* vb = Vth + (8 * w + gid) * 72 + c0;
            const __nv_bfloat16* vl = Vtl + (8 * w + gid) * 72 + c0;
            const unsigned bh0 = *(const unsigned*)vb;
            const unsigned bh1 = *(const unsigned*)(vb + 8);
            const unsigned bl0 = *(const unsigned*)vl;
            const unsigned bl1 = *(const unsigned*)(vl + 8);

            mma16(o, ah, bh0, bh1);
            mma16(o, al, bh0, bh1);
            mma16(o, ah, bl0, bl1);
        }
    }

    // ---- total l across warps, write output -------------------------------
    if (qid == 0) { lsum[w][gid] = l0; lsum[w][gid + 8] = l1; }
    __syncthreads();
    float lt0 = 0.f, lt1 = 0.f;
    #pragma unroll
    for (int ww = 0; ww < 8; ++ww) {
        lt0 += lsum[ww][gid];
        lt1 += lsum[ww][gid + 8];
    }
    float* ob = Out + t * 1024;
    const int c = 8 * w + 2 * qid;
    *(float2*)(ob + gid * 64 + c)       = make_float2(o[0] / lt0, o[1] / lt0);
    *(float2*)(ob + (gid + 8) * 64 + c) = make_float2(o[2] / lt1, o[3] / lt1);
}

extern "C" void kernel_launch(void* const* d_in, const int* in_sizes, int n_in,
                              void* d_out, int out_size) {
    const float* Q  = (const float*)d_in[0];
    const float* K  = (const float*)d_in[1];
    const float* V  = (const float*)d_in[2];
    const int*   BI = (const int*)d_in[3];
    split_kernel<<<512, 256>>>(K, V);
    nsa_bf16<<<TT, 256>>>(Q, BI, (float*)d_out);
}

// round 4
// speedup vs baseline: 4.0949x; 2.3032x over previous
#include <cuda_runtime.h>
#include <cuda_bf16.h>
#include <math.h>

#define TT 2048

// Fragment-ordered bf16 hi/lo splits: [blk][w][ks][lane] -> int4 {b0h,b1h,b0l,b1l}
__device__ int4 g_KQ[32 * 8 * 4 * 32];   // 512 KB
__device__ int4 g_VP[32 * 8 * 4 * 32];   // 512 KB

__device__ __forceinline__ unsigned pack_hi(float x, float y, float& rx, float& ry) {
    __nv_bfloat162 h = __float22bfloat162_rn(make_float2(x, y));
    rx = x - __low2float(h);
    ry = y - __high2float(h);
    return *(unsigned*)&h;
}
__device__ __forceinline__ unsigned pack2(float x, float y) {
    __nv_bfloat162 h = __float22bfloat162_rn(make_float2(x, y));
    return *(unsigned*)&h;
}

__global__ void __launch_bounds__(256) pack_kernel(
    const float* __restrict__ K, const float* __restrict__ V)
{
    const int i    = blockIdx.x * 256 + threadIdx.x;   // 0..32767
    const int lane = i & 31;
    const int ks   = (i >> 5) & 3;
    const int w    = (i >> 7) & 7;
    const int blk  = i >> 10;
    const int gid  = lane >> 2, qid = lane & 3;
    const int r    = 8 * w + gid;            // key row (K) / dim row (Vt)
    const int c0   = 16 * ks + 2 * qid;

    const float* Kb = K + blk * 4096;
    const float* Vb = V + blk * 4096;

    float r0, r1, r2, r3;
    unsigned kh0 = pack_hi(Kb[r * 64 + c0],     Kb[r * 64 + c0 + 1], r0, r1);
    unsigned kh1 = pack_hi(Kb[r * 64 + c0 + 8], Kb[r * 64 + c0 + 9], r2, r3);
    g_KQ[i] = make_int4((int)kh0, (int)kh1, (int)pack2(r0, r1), (int)pack2(r2, r3));

    // Vt[r][c] = V[c][r] within the block
    unsigned vh0 = pack_hi(Vb[c0 * 64 + r],       Vb[(c0 + 1) * 64 + r], r0, r1);
    unsigned vh1 = pack_hi(Vb[(c0 + 8) * 64 + r], Vb[(c0 + 9) * 64 + r], r2, r3);
    g_VP[i] = make_int4((int)vh0, (int)vh1, (int)pack2(r0, r1), (int)pack2(r2, r3));
}

__device__ __forceinline__ void mma16(float c[4], const unsigned a[4],
                                      int b0, int b1) {
    asm volatile(
        "mma.sync.aligned.m16n8k16.row.col.f32.bf16.bf16.f32 "
        "{%0,%1,%2,%3}, {%4,%5,%6,%7}, {%8,%9}, {%0,%1,%2,%3};\n"
        : "+f"(c[0]), "+f"(c[1]), "+f"(c[2]), "+f"(c[3])
        : "r"(a[0]), "r"(a[1]), "r"(a[2]), "r"(a[3]), "r"(b0), "r"(b1));
}

// One CTA per token, 8 warps. No K/V SMEM: MMA B-operands come straight from
// the fragment-ordered global arrays (L2-resident). QK n-split / PV d-split.
__global__ void __launch_bounds__(256, 3) nsa4(
    const float* __restrict__ Q,   // [T,16,64]
    const int*   __restrict__ BI,  // [T,16]
    float* __restrict__ Out)       // [T,16,64]
{
    __shared__ unsigned Qhi[16 * 36];   // Q hi pairs, row stride 36 (72 bf16)
    __shared__ unsigned Qlo[16 * 36];   // Q lo pairs (A-frags read per use)
    __shared__ unsigned Phu[16 * 36];   // P hi pairs
    __shared__ unsigned Plu[16 * 36];   // P lo pairs
    __shared__ float pmax[8][16];
    __shared__ float lsum[8][16];

    const int t    = blockIdx.x;
    const int tid  = threadIdx.x;
    const int w    = tid >> 5;
    const int lane = tid & 31;
    const int gid  = lane >> 2;
    const int qid  = lane & 3;

    // ---- prologue: stage Q hi/lo (scaled) to SMEM, then pick up hi frags --
    {
        float4 qv = ((const float4*)(Q + t * 1024))[tid];
        qv.x *= 0.125f; qv.y *= 0.125f; qv.z *= 0.125f; qv.w *= 0.125f;
        float l0, l1, l2, l3;
        unsigned h0 = pack_hi(qv.x, qv.y, l0, l1);
        unsigned h1 = pack_hi(qv.z, qv.w, l2, l3);
        const int row = tid >> 4, cp = (tid & 15) * 2;   // pair index 0..31
        Qhi[row * 36 + cp]     = h0;
        Qhi[row * 36 + cp + 1] = h1;
        Qlo[row * 36 + cp]     = pack2(l0, l1);
        Qlo[row * 36 + cp + 1] = pack2(l2, l3);
    }
    __syncthreads();

    unsigned qh[4][4];
    #pragma unroll
    for (int ks = 0; ks < 4; ++ks) {
        const int b0 = gid * 36 + 8 * ks + qid;
        const int b1 = (gid + 8) * 36 + 8 * ks + qid;
        qh[ks][0] = Qhi[b0];
        qh[ks][1] = Qhi[b1];
        qh[ks][2] = Qhi[b0 + 4];
        qh[ks][3] = Qhi[b1 + 4];
    }

    float o[4] = {0.f, 0.f, 0.f, 0.f};
    float m0 = -INFINITY, m1 = -INFINITY, l0 = 0.f, l1 = 0.f;

    int blk = __ldg(BI + t * 16);
    int4 kq[4];
    #pragma unroll
    for (int ks = 0; ks < 4; ++ks)
        kq[ks] = g_KQ[(blk * 8 + w) * 128 + ks * 32 + lane];

    for (int s = 0; s < 16; ++s) {
        const int blkc = blk;
        const int nxt  = (s < 15) ? __ldg(BI + t * 16 + s + 1) : 0;

        // ---- QK: 3-term bf16 emulation, B straight from registers ---------
        float sc[4] = {0.f, 0.f, 0.f, 0.f};
        #pragma unroll
        for (int ks = 0; ks < 4; ++ks) {
            unsigned al[4];
            const int b0 = gid * 36 + 8 * ks + qid;
            const int b1 = (gid + 8) * 36 + 8 * ks + qid;
            al[0] = Qlo[b0]; al[1] = Qlo[b1];
            al[2] = Qlo[b0 + 4]; al[3] = Qlo[b1 + 4];
            mma16(sc, qh[ks], kq[ks].x, kq[ks].y);
            mma16(sc, al,     kq[ks].x, kq[ks].y);
            mma16(sc, qh[ks], kq[ks].z, kq[ks].w);
        }

        // ---- causal mask ---------------------------------------------------
        {
            const int kp = blkc * 64 + 8 * w + 2 * qid;
            if (kp     > t) { sc[0] = -INFINITY; sc[2] = -INFINITY; }
            if (kp + 1 > t) { sc[1] = -INFINITY; sc[3] = -INFINITY; }
        }

        // ---- per-warp row max -> CTA exchange ------------------------------
        float r0 = fmaxf(sc[0], sc[1]);
        r0 = fmaxf(r0, __shfl_xor_sync(0xffffffffu, r0, 1));
        r0 = fmaxf(r0, __shfl_xor_sync(0xffffffffu, r0, 2));
        float r1 = fmaxf(sc[2], sc[3]);
        r1 = fmaxf(r1, __shfl_xor_sync(0xffffffffu, r1, 1));
        r1 = fmaxf(r1, __shfl_xor_sync(0xffffffffu, r1, 2));
        if (qid == 0) { pmax[w][gid] = r0; pmax[w][gid + 8] = r1; }
        __syncthreads();   // sync1: pmax ready; also Ph WAR vs prev PV reads

        float bm0 = m0, bm1 = m1;
        #pragma unroll
        for (int ww = 0; ww < 8; ++ww) {
            bm0 = fmaxf(bm0, pmax[ww][gid]);
            bm1 = fmaxf(bm1, pmax[ww][gid + 8]);
        }
        const float s0 = (bm0 == -INFINITY) ? 0.f : bm0;
        const float s1 = (bm1 == -INFINITY) ? 0.f : bm1;
        const float corr0 = __expf(m0 - s0);
        const float corr1 = __expf(m1 - s1);

        const float p0 = __expf(sc[0] - s0);
        const float p1 = __expf(sc[1] - s0);
        const float p2 = __expf(sc[2] - s1);
        const float p3 = __expf(sc[3] - s1);

        // ---- issue V fragment loads now; bar-wait below hides their latency
        int4 vp[4];
        #pragma unroll
        for (int ks = 0; ks < 4; ++ks)
            vp[ks] = g_VP[(blkc * 8 + w) * 128 + ks * 32 + lane];

        float pl0 = p0 + p1;
        pl0 += __shfl_xor_sync(0xffffffffu, pl0, 1);
        pl0 += __shfl_xor_sync(0xffffffffu, pl0, 2);
        float pl1 = p2 + p3;
        pl1 += __shfl_xor_sync(0xffffffffu, pl1, 1);
        pl1 += __shfl_xor_sync(0xffffffffu, pl1, 2);
        l0 = l0 * corr0 + pl0;
        l1 = l1 * corr1 + pl1;
        m0 = bm0; m1 = bm1;
        o[0] *= corr0; o[1] *= corr0; o[2] *= corr1; o[3] *= corr1;

        // ---- publish P hi/lo pairs -----------------------------------------
        {
            float lx, ly;
            unsigned h01 = pack_hi(p0, p1, lx, ly);
            unsigned l01 = pack2(lx, ly);
            unsigned h23 = pack_hi(p2, p3, lx, ly);
            unsigned l23 = pack2(lx, ly);
            const int c = 4 * w + qid;            // pair column
            Phu[gid * 36 + c]       = h01;
            Plu[gid * 36 + c]       = l01;
            Phu[(gid + 8) * 36 + c] = h23;
            Plu[(gid + 8) * 36 + c] = l23;
        }
        __syncthreads();   // sync2: P visible to all warps

        // ---- prefetch next block's K fragments under the PV MMAs ----------
        #pragma unroll
        for (int ks = 0; ks < 4; ++ks)
            kq[ks] = g_KQ[(nxt * 8 + w) * 128 + ks * 32 + lane];

        // ---- PV: A = P (SMEM), B = V fragments (registers) ----------------
        #pragma unroll
        for (int ks = 0; ks < 4; ++ks) {
            unsigned ah[4], al[4];
            const int b0 = gid * 36 + 8 * ks + qid;
            const int b1 = (gid + 8) * 36 + 8 * ks + qid;
            ah[0] = Phu[b0]; ah[1] = Phu[b1];
            ah[2] = Phu[b0 + 4]; ah[3] = Phu[b1 + 4];
            al[0] = Plu[b0]; al[1] = Plu[b1];
            al[2] = Plu[b0 + 4]; al[3] = Plu[b1 + 4];
            mma16(o, ah, vp[ks].x, vp[ks].y);
            mma16(o, al, vp[ks].x, vp[ks].y);
            mma16(o, ah, vp[ks].z, vp[ks].w);
        }

        blk = nxt;
    }

    // ---- merge l across warps, normalize, write ---------------------------
    if (qid == 0) { lsum[w][gid] = l0; lsum[w][gid + 8] = l1; }
    __syncthreads();
    float lt0 = 0.f, lt1 = 0.f;
    #pragma unroll
    for (int ww = 0; ww < 8; ++ww) {
        lt0 += lsum[ww][gid];
        lt1 += lsum[ww][gid + 8];
    }
    float* ob = Out + t * 1024;
    const int c = 8 * w + 2 * qid;
    *(float2*)(ob + gid * 64 + c)       = make_float2(o[0] / lt0, o[1] / lt0);
    *(float2*)(ob + (gid + 8) * 64 + c) = make_float2(o[2] / lt1, o[3] / lt1);
}

extern "C" void kernel_launch(void* const* d_in, const int* in_sizes, int n_in,
                              void* d_out, int out_size) {
    const float* Q  = (const float*)d_in[0];
    const float* K  = (const float*)d_in[1];
    const float* V  = (const float*)d_in[2];
    const int*   BI = (const int*)d_in[3];
    pack_kernel<<<128, 256>>>(K, V);
    nsa4<<<TT, 256>>>(Q, BI, (float*)d_out);
}

// round 5
// speedup vs baseline: 4.7502x; 1.1600x over previous
#include <cuda_runtime.h>
#include <cuda_fp16.h>
#include <math.h>

#define TT 2048

// Fragment-ordered plain-fp16 K and V(transposed):
// [blk][w][p][lane] -> int4 {b0(2p), b1(2p), b0(2p+1), b1(2p+1)}  (fp16x2 each)
__device__ int4 g_K[32 * 8 * 2 * 32];   // 256 KB
__device__ int4 g_V[32 * 8 * 2 * 32];   // 256 KB

__device__ __forceinline__ unsigned h2(float x, float y) {
    __half2 h = __floats2half2_rn(x, y);
    return *(unsigned*)&h;
}

__global__ void __launch_bounds__(256) pack_kernel(
    const float* __restrict__ K, const float* __restrict__ V)
{
    const int i    = blockIdx.x * 256 + threadIdx.x;   // 0..16383
    const int lane = i & 31;
    const int p    = (i >> 5) & 1;
    const int w    = (i >> 6) & 7;
    const int blk  = i >> 9;
    const int gid  = lane >> 2, qid = lane & 3;
    const int r    = 8 * w + gid;          // key row (K) / dim row (Vt)
    const int c0   = 32 * p + 2 * qid;     // ks = 2p
    const int c1   = c0 + 16;              // ks = 2p+1

    const float* Kb = K + blk * 4096;
    const float* Vb = V + blk * 4096;

    g_K[i] = make_int4(
        (int)h2(Kb[r * 64 + c0],      Kb[r * 64 + c0 + 1]),
        (int)h2(Kb[r * 64 + c0 + 8],  Kb[r * 64 + c0 + 9]),
        (int)h2(Kb[r * 64 + c1],      Kb[r * 64 + c1 + 1]),
        (int)h2(Kb[r * 64 + c1 + 8],  Kb[r * 64 + c1 + 9]));

    // Vt[r][c] = V[c][r]
    g_V[i] = make_int4(
        (int)h2(Vb[c0 * 64 + r],       Vb[(c0 + 1) * 64 + r]),
        (int)h2(Vb[(c0 + 8) * 64 + r], Vb[(c0 + 9) * 64 + r]),
        (int)h2(Vb[c1 * 64 + r],       Vb[(c1 + 1) * 64 + r]),
        (int)h2(Vb[(c1 + 8) * 64 + r], Vb[(c1 + 9) * 64 + r]));
}

__device__ __forceinline__ void mma16(float c[4], const int4 a, int b0, int b1) {
    asm volatile(
        "mma.sync.aligned.m16n8k16.row.col.f32.f16.f16.f32 "
        "{%0,%1,%2,%3}, {%4,%5,%6,%7}, {%8,%9}, {%0,%1,%2,%3};\n"
        : "+f"(c[0]), "+f"(c[1]), "+f"(c[2]), "+f"(c[3])
        : "r"(a.x), "r"(a.y), "r"(a.z), "r"(a.w), "r"(b0), "r"(b1));
}

// One CTA per token, 8 warps. QK n-split / PV d-split, all operands fp16.
// Q and P split hi+lo (2-term emulation); K and V plain fp16.
__global__ void __launch_bounds__(256, 4) nsa5(
    const float* __restrict__ Q,   // [T,16,64]
    const int*   __restrict__ BI,  // [T,16]
    float* __restrict__ Out)       // [T,16,64]
{
    __shared__ int4 QhF[4 * 32];    // Q hi A-frags  [ks][lane]
    __shared__ int4 QlF[4 * 32];    // Q lo A-frags
    __shared__ int4 PhF[4 * 32];    // P hi A-frags
    __shared__ int4 PlF[4 * 32];    // P lo A-frags
    __shared__ float pmaxT[16][8];  // [head][warp]
    __shared__ float lsumT[16][8];

    const int t    = blockIdx.x;
    const int tid  = threadIdx.x;
    const int w    = tid >> 5;
    const int lane = tid & 31;
    const int gid  = lane >> 2;
    const int qid  = lane & 3;

    // ---- prologue: build Q A-fragments (scaled, fp16 hi/lo) ---------------
    {
        const int half = tid >> 7;          // 0 = hi, 1 = lo
        const int f    = tid & 127;         // frag slot
        const int fks  = f >> 5, fl = f & 31;
        const int fg   = fl >> 2, fq = fl & 3;
        const int c0   = 16 * fks + 2 * fq;
        const float* Qp = Q + t * 1024;
        float2 x0 = *(const float2*)(Qp + fg * 64 + c0);
        float2 x1 = *(const float2*)(Qp + (fg + 8) * 64 + c0);
        float2 x2 = *(const float2*)(Qp + fg * 64 + c0 + 8);
        float2 x3 = *(const float2*)(Qp + (fg + 8) * 64 + c0 + 8);
        x0.x *= 0.125f; x0.y *= 0.125f; x1.x *= 0.125f; x1.y *= 0.125f;
        x2.x *= 0.125f; x2.y *= 0.125f; x3.x *= 0.125f; x3.y *= 0.125f;
        __half2 h0 = __floats2half2_rn(x0.x, x0.y);
        __half2 h1 = __floats2half2_rn(x1.x, x1.y);
        __half2 h2v = __floats2half2_rn(x2.x, x2.y);
        __half2 h3 = __floats2half2_rn(x3.x, x3.y);
        if (half == 0) {
            QhF[f] = make_int4(*(int*)&h0, *(int*)&h1, *(int*)&h2v, *(int*)&h3);
        } else {
            QlF[f] = make_int4(
                (int)h2(x0.x - __low2float(h0),  x0.y - __high2float(h0)),
                (int)h2(x1.x - __low2float(h1),  x1.y - __high2float(h1)),
                (int)h2(x2.x - __low2float(h2v), x2.y - __high2float(h2v)),
                (int)h2(x3.x - __low2float(h3),  x3.y - __high2float(h3)));
        }
    }
    __syncthreads();

    float o[4] = {0.f, 0.f, 0.f, 0.f};
    float m0 = -INFINITY, m1 = -INFINITY, l0 = 0.f, l1 = 0.f;

    int blk = __ldg(BI + t * 16);
    int4 kq0 = g_K[(blk * 8 + w) * 64 + lane];
    int4 kq1 = g_K[(blk * 8 + w) * 64 + 32 + lane];

    for (int s = 0; s < 16; ++s) {
        const int blkc = blk;
        const int nxt  = (s < 15) ? __ldg(BI + t * 16 + s + 1) : 0;

        // ---- QK: 2-term fp16 (Qh + Ql) x plain-fp16 K ---------------------
        float sc[4] = {0.f, 0.f, 0.f, 0.f};
        {
            int4 ah, al;
            ah = QhF[lane];        al = QlF[lane];
            mma16(sc, ah, kq0.x, kq0.y);  mma16(sc, al, kq0.x, kq0.y);
            ah = QhF[32 + lane];   al = QlF[32 + lane];
            mma16(sc, ah, kq0.z, kq0.w);  mma16(sc, al, kq0.z, kq0.w);
            ah = QhF[64 + lane];   al = QlF[64 + lane];
            mma16(sc, ah, kq1.x, kq1.y);  mma16(sc, al, kq1.x, kq1.y);
            ah = QhF[96 + lane];   al = QlF[96 + lane];
            mma16(sc, ah, kq1.z, kq1.w);  mma16(sc, al, kq1.z, kq1.w);
        }

        // ---- causal mask --------------------------------------------------
        {
            const int kp = blkc * 64 + 8 * w + 2 * qid;
            if (kp     > t) { sc[0] = -INFINITY; sc[2] = -INFINITY; }
            if (kp + 1 > t) { sc[1] = -INFINITY; sc[3] = -INFINITY; }
        }

        // ---- per-warp row max -> CTA exchange -----------------------------
        float r0 = fmaxf(sc[0], sc[1]);
        r0 = fmaxf(r0, __shfl_xor_sync(0xffffffffu, r0, 1));
        r0 = fmaxf(r0, __shfl_xor_sync(0xffffffffu, r0, 2));
        float r1 = fmaxf(sc[2], sc[3]);
        r1 = fmaxf(r1, __shfl_xor_sync(0xffffffffu, r1, 1));
        r1 = fmaxf(r1, __shfl_xor_sync(0xffffffffu, r1, 2));
        if (qid == 0) { pmaxT[gid][w] = r0; pmaxT[gid + 8][w] = r1; }
        __syncthreads();   // sync1

        float bm0 = m0, bm1 = m1;
        {
            const float4* pa = (const float4*)pmaxT[gid];
            const float4* pb = (const float4*)pmaxT[gid + 8];
            float4 a0 = pa[0], a1 = pa[1], b0 = pb[0], b1 = pb[1];
            bm0 = fmaxf(bm0, fmaxf(fmaxf(a0.x, a0.y), fmaxf(a0.z, a0.w)));
            bm0 = fmaxf(bm0, fmaxf(fmaxf(a1.x, a1.y), fmaxf(a1.z, a1.w)));
            bm1 = fmaxf(bm1, fmaxf(fmaxf(b0.x, b0.y), fmaxf(b0.z, b0.w)));
            bm1 = fmaxf(bm1, fmaxf(fmaxf(b1.x, b1.y), fmaxf(b1.z, b1.w)));
        }
        const float s0 = (bm0 == -INFINITY) ? 0.f : bm0;
        const float s1 = (bm1 == -INFINITY) ? 0.f : bm1;
        const float corr0 = __expf(m0 - s0);
        const float corr1 = __expf(m1 - s1);

        const float p0 = __expf(sc[0] - s0);
        const float p1 = __expf(sc[1] - s0);
        const float p2 = __expf(sc[2] - s1);
        const float p3 = __expf(sc[3] - s1);

        // ---- issue V loads now; barriers below hide their latency ---------
        int4 vp0 = g_V[(blkc * 8 + w) * 64 + lane];
        int4 vp1 = g_V[(blkc * 8 + w) * 64 + 32 + lane];

        float pl0 = p0 + p1;
        pl0 += __shfl_xor_sync(0xffffffffu, pl0, 1);
        pl0 += __shfl_xor_sync(0xffffffffu, pl0, 2);
        float pl1 = p2 + p3;
        pl1 += __shfl_xor_sync(0xffffffffu, pl1, 1);
        pl1 += __shfl_xor_sync(0xffffffffu, pl1, 2);
        l0 = l0 * corr0 + pl0;
        l1 = l1 * corr1 + pl1;
        m0 = bm0; m1 = bm1;
        o[0] *= corr0; o[1] *= corr0; o[2] *= corr1; o[3] *= corr1;

        // ---- publish P as A-fragments (hi/lo fp16) ------------------------
        {
            __half2 hh01 = __floats2half2_rn(p0, p1);
            __half2 hh23 = __floats2half2_rn(p2, p3);
            unsigned uh01 = *(unsigned*)&hh01;
            unsigned uh23 = *(unsigned*)&hh23;
            unsigned ul01 = h2(p0 - __low2float(hh01), p1 - __high2float(hh01));
            unsigned ul23 = h2(p2 - __low2float(hh23), p3 - __high2float(hh23));
            // frag slot: ks' = w>>1, lane' = lane; comps: even w -> x,y; odd -> z,w
            const int base = ((w >> 1) * 32 + lane) * 4 + (w & 1) * 2;
            ((unsigned*)PhF)[base]     = uh01;
            ((unsigned*)PhF)[base + 1] = uh23;
            ((unsigned*)PlF)[base]     = ul01;
            ((unsigned*)PlF)[base + 1] = ul23;
        }
        __syncthreads();   // sync2

        // ---- prefetch next block's K frags under the PV MMAs --------------
        kq0 = g_K[(nxt * 8 + w) * 64 + lane];
        kq1 = g_K[(nxt * 8 + w) * 64 + 32 + lane];

        // ---- PV: A = P frags (SMEM), B = V frags (regs) -------------------
        {
            int4 ah, al;
            ah = PhF[lane];        al = PlF[lane];
            mma16(o, ah, vp0.x, vp0.y);  mma16(o, al, vp0.x, vp0.y);
            ah = PhF[32 + lane];   al = PlF[32 + lane];
            mma16(o, ah, vp0.z, vp0.w);  mma16(o, al, vp0.z, vp0.w);
            ah = PhF[64 + lane];   al = PlF[64 + lane];
            mma16(o, ah, vp1.x, vp1.y);  mma16(o, al, vp1.x, vp1.y);
            ah = PhF[96 + lane];   al = PlF[96 + lane];
            mma16(o, ah, vp1.z, vp1.w);  mma16(o, al, vp1.z, vp1.w);
        }

        blk = nxt;
    }

    // ---- merge l across warps, normalize, write ---------------------------
    if (qid == 0) { lsumT[gid][w] = l0; lsumT[gid + 8][w] = l1; }
    __syncthreads();
    float lt0, lt1;
    {
        const float4* pa = (const float4*)lsumT[gid];
        const float4* pb = (const float4*)lsumT[gid + 8];
        float4 a0 = pa[0], a1 = pa[1], b0 = pb[0], b1 = pb[1];
        lt0 = (a0.x + a0.y + a0.z + a0.w) + (a1.x + a1.y + a1.z + a1.w);
        lt1 = (b0.x + b0.y + b0.z + b0.w) + (b1.x + b1.y + b1.z + b1.w);
    }
    float* ob = Out + t * 1024;
    const int c = 8 * w + 2 * qid;
    *(float2*)(ob + gid * 64 + c)       = make_float2(o[0] / lt0, o[1] / lt0);
    *(float2*)(ob + (gid + 8) * 64 + c) = make_float2(o[2] / lt1, o[3] / lt1);
}

extern "C" void kernel_launch(void* const* d_in, const int* in_sizes, int n_in,
                              void* d_out, int out_size) {
    const float* Q  = (const float*)d_in[0];
    const float* K  = (const float*)d_in[1];
    const float* V  = (const float*)d_in[2];
    const int*   BI = (const int*)d_in[3];
    pack_kernel<<<64, 256>>>(K, V);
    nsa5<<<TT, 256>>>(Q, BI, (float*)d_out);
}

// round 6
// speedup vs baseline: 7.5982x; 1.5996x over previous
#include <cuda_runtime.h>
#include <cuda_fp16.h>
#include <math.h>

#define TT 2048

// Fragment-ordered plain-fp16 K and V(transposed), identical layout to R5:
// [blk][nt][p][lane] -> int4 {b0(2p),b1(2p),b0(2p+1),b1(2p+1)} (fp16x2 each)
__device__ int4 g_K[32 * 8 * 2 * 32];   // 256 KB
__device__ int4 g_V[32 * 8 * 2 * 32];   // 256 KB

__device__ __forceinline__ unsigned h2u(float x, float y) {
    __half2 h = __floats2half2_rn(x, y);
    return *(unsigned*)&h;
}

__global__ void __launch_bounds__(256) pack_kernel(
    const float* __restrict__ K, const float* __restrict__ V)
{
    const int i    = blockIdx.x * 256 + threadIdx.x;   // 0..16383
    const int lane = i & 31;
    const int p    = (i >> 5) & 1;
    const int nt   = (i >> 6) & 7;
    const int blk  = i >> 9;
    const int gid  = lane >> 2, qid = lane & 3;
    const int r    = 8 * nt + gid;         // key row (K) / dim row (Vt)
    const int c0   = 32 * p + 2 * qid;     // ks = 2p
    const int c1   = c0 + 16;              // ks = 2p+1

    const float* Kb = K + blk * 4096;
    const float* Vb = V + blk * 4096;

    g_K[i] = make_int4(
        (int)h2u(Kb[r * 64 + c0],      Kb[r * 64 + c0 + 1]),
        (int)h2u(Kb[r * 64 + c0 + 8],  Kb[r * 64 + c0 + 9]),
        (int)h2u(Kb[r * 64 + c1],      Kb[r * 64 + c1 + 1]),
        (int)h2u(Kb[r * 64 + c1 + 8],  Kb[r * 64 + c1 + 9]));

    g_V[i] = make_int4(
        (int)h2u(Vb[c0 * 64 + r],       Vb[(c0 + 1) * 64 + r]),
        (int)h2u(Vb[(c0 + 8) * 64 + r], Vb[(c0 + 9) * 64 + r]),
        (int)h2u(Vb[c1 * 64 + r],       Vb[(c1 + 1) * 64 + r]),
        (int)h2u(Vb[(c1 + 8) * 64 + r], Vb[(c1 + 9) * 64 + r]));
}

__device__ __forceinline__ void mma16(float c[4], const int4 a, int b0, int b1) {
    asm volatile(
        "mma.sync.aligned.m16n8k16.row.col.f32.f16.f16.f32 "
        "{%0,%1,%2,%3}, {%4,%5,%6,%7}, {%8,%9}, {%0,%1,%2,%3};\n"
        : "+f"(c[0]), "+f"(c[1]), "+f"(c[2]), "+f"(c[3])
        : "r"(a.x), "r"(a.y), "r"(a.z), "r"(a.w), "r"(b0), "r"(b1));
}

// One WARP per token (1-warp CTAs). The warp computes all 16 heads x 64 keys:
// QK n-tiles 0..7, then softmax fully in registers, then PV with the P
// C-fragments re-interpreted in-place as A-fragments. No SMEM, no barriers.
// K/V fragments stream through a rotating 4-int4 buffer spanning phases.
__global__ void __launch_bounds__(32, 14) nsa6(
    const float* __restrict__ Q,   // [T,16,64]
    const int*   __restrict__ BI,  // [T,16]
    float* __restrict__ Out)       // [T,16,64]
{
    const int t    = blockIdx.x;
    const int lane = threadIdx.x;
    const int gid  = lane >> 2;
    const int qid  = lane & 3;

    // ---- Q A-fragments (scaled, fp16 hi+lo), resident in registers --------
    int4 Qh[4], Ql[4];
    {
        const float* Qp = Q + t * 1024;
        #pragma unroll
        for (int ks = 0; ks < 4; ++ks) {
            const int c0 = 16 * ks + 2 * qid;
            float2 x0 = *(const float2*)(Qp + gid * 64 + c0);
            float2 x1 = *(const float2*)(Qp + (gid + 8) * 64 + c0);
            float2 x2 = *(const float2*)(Qp + gid * 64 + c0 + 8);
            float2 x3 = *(const float2*)(Qp + (gid + 8) * 64 + c0 + 8);
            x0.x *= 0.125f; x0.y *= 0.125f; x1.x *= 0.125f; x1.y *= 0.125f;
            x2.x *= 0.125f; x2.y *= 0.125f; x3.x *= 0.125f; x3.y *= 0.125f;
            __half2 h0 = __floats2half2_rn(x0.x, x0.y);
            __half2 h1 = __floats2half2_rn(x1.x, x1.y);
            __half2 hv2 = __floats2half2_rn(x2.x, x2.y);
            __half2 h3 = __floats2half2_rn(x3.x, x3.y);
            Qh[ks] = make_int4(*(int*)&h0, *(int*)&h1, *(int*)&hv2, *(int*)&h3);
            Ql[ks] = make_int4(
                (int)h2u(x0.x - __low2float(h0),  x0.y - __high2float(h0)),
                (int)h2u(x1.x - __low2float(h1),  x1.y - __high2float(h1)),
                (int)h2u(x2.x - __low2float(hv2), x2.y - __high2float(hv2)),
                (int)h2u(x3.x - __low2float(h3),  x3.y - __high2float(h3)));
        }
    }

    float o[8][4];
    #pragma unroll
    for (int nt = 0; nt < 8; ++nt)
        o[nt][0] = o[nt][1] = o[nt][2] = o[nt][3] = 0.f;
    float m0 = -INFINITY, m1 = -INFINITY, l0 = 0.f, l1 = 0.f;

    const int* bip = BI + t * 16;
    int blk = __ldg(bip);

    // Rotating stream buffer: cur = (c0a,c0b), next = (c1a,c1b).
    int4 c0a, c0b, c1a, c1b;
    {
        const int4* KB = g_K + (size_t)blk * 512;
        c0a = KB[lane];       c0b = KB[32 + lane];    // K nt0
        c1a = KB[64 + lane];  c1b = KB[96 + lane];    // K nt1
    }

    #pragma unroll 1
    for (int s = 0; s < 16; ++s) {
        const int blkc = blk;
        const int nxt  = (s < 15) ? __ldg(bip + s + 1) : 0;
        const int4* Kb = g_K + (size_t)blkc * 512;
        const int4* Vb = g_V + (size_t)blkc * 512;
        const int4* Kn = g_K + (size_t)nxt * 512;

        // ---- QK: 8 n-tiles, 2-term fp16 Q x plain-fp16 K ------------------
        float sc[8][4];
        #pragma unroll
        for (int nt = 0; nt < 8; ++nt) {
            const int4 ba = c0a, bb = c0b;
            c0a = c1a; c0b = c1b;
            if (nt < 6) {
                c1a = Kb[(nt + 2) * 64 + lane];
                c1b = Kb[(nt + 2) * 64 + 32 + lane];
            } else {        // stream wraps into V0, V1
                c1a = Vb[(nt - 6) * 64 + lane];
                c1b = Vb[(nt - 6) * 64 + 32 + lane];
            }
            float a[4] = {0.f, 0.f, 0.f, 0.f};
            mma16(a, Qh[0], ba.x, ba.y);  mma16(a, Ql[0], ba.x, ba.y);
            mma16(a, Qh[1], ba.z, ba.w);  mma16(a, Ql[1], ba.z, ba.w);
            mma16(a, Qh[2], bb.x, bb.y);  mma16(a, Ql[2], bb.x, bb.y);
            mma16(a, Qh[3], bb.z, bb.w);  mma16(a, Ql[3], bb.z, bb.w);
            const int kp = blkc * 64 + 8 * nt + 2 * qid;
            sc[nt][0] = (kp     <= t) ? a[0] : -INFINITY;
            sc[nt][1] = (kp + 1 <= t) ? a[1] : -INFINITY;
            sc[nt][2] = (kp     <= t) ? a[2] : -INFINITY;
            sc[nt][3] = (kp + 1 <= t) ? a[3] : -INFINITY;
        }

        // ---- softmax (rows gid -> m0, gid+8 -> m1), all in-warp -----------
        float bm0 = m0, bm1 = m1;
        #pragma unroll
        for (int nt = 0; nt < 8; ++nt) {
            bm0 = fmaxf(bm0, fmaxf(sc[nt][0], sc[nt][1]));
            bm1 = fmaxf(bm1, fmaxf(sc[nt][2], sc[nt][3]));
        }
        bm0 = fmaxf(bm0, __shfl_xor_sync(0xffffffffu, bm0, 1));
        bm0 = fmaxf(bm0, __shfl_xor_sync(0xffffffffu, bm0, 2));
        bm1 = fmaxf(bm1, __shfl_xor_sync(0xffffffffu, bm1, 1));
        bm1 = fmaxf(bm1, __shfl_xor_sync(0xffffffffu, bm1, 2));
        const float s0 = (bm0 == -INFINITY) ? 0.f : bm0;
        const float s1 = (bm1 == -INFINITY) ? 0.f : bm1;
        const float corr0 = __expf(m0 - s0);
        const float corr1 = __expf(m1 - s1);
        m0 = bm0; m1 = bm1;

        // ---- exp -> P A-fragments (hi+lo) entirely in registers -----------
        int4 Ph[4], Pl[4];
        float pl0 = 0.f, pl1 = 0.f;
        #pragma unroll
        for (int p = 0; p < 4; ++p) {       // p == PV k-step; n-tiles 2p,2p+1
            unsigned hbits[4], lbits[4];
            #pragma unroll
            for (int j = 0; j < 2; ++j) {
                const int nt = 2 * p + j;
                const float e0 = __expf(sc[nt][0] - s0);
                const float e1 = __expf(sc[nt][1] - s0);
                const float e2 = __expf(sc[nt][2] - s1);
                const float e3 = __expf(sc[nt][3] - s1);
                pl0 += e0 + e1;
                pl1 += e2 + e3;
                __half2 hh01 = __floats2half2_rn(e0, e1);
                __half2 hh23 = __floats2half2_rn(e2, e3);
                hbits[2 * j]     = *(unsigned*)&hh01;
                hbits[2 * j + 1] = *(unsigned*)&hh23;
                lbits[2 * j]     = h2u(e0 - __low2float(hh01), e1 - __high2float(hh01));
                lbits[2 * j + 1] = h2u(e2 - __low2float(hh23), e3 - __high2float(hh23));
            }
            Ph[p] = make_int4((int)hbits[0], (int)hbits[1], (int)hbits[2], (int)hbits[3]);
            Pl[p] = make_int4((int)lbits[0], (int)lbits[1], (int)lbits[2], (int)lbits[3]);
        }
        pl0 += __shfl_xor_sync(0xffffffffu, pl0, 1);
        pl0 += __shfl_xor_sync(0xffffffffu, pl0, 2);
        pl1 += __shfl_xor_sync(0xffffffffu, pl1, 1);
        pl1 += __shfl_xor_sync(0xffffffffu, pl1, 2);
        l0 = l0 * corr0 + pl0;
        l1 = l1 * corr1 + pl1;
        #pragma unroll
        for (int nt = 0; nt < 8; ++nt) {
            o[nt][0] *= corr0; o[nt][1] *= corr0;
            o[nt][2] *= corr1; o[nt][3] *= corr1;
        }

        // ---- PV: 8 d-tiles; stream wraps into next block's K0, K1 ---------
        #pragma unroll
        for (int nt = 0; nt < 8; ++nt) {
            const int4 ba = c0a, bb = c0b;
            c0a = c1a; c0b = c1b;
            if (nt < 6) {
                c1a = Vb[(nt + 2) * 64 + lane];
                c1b = Vb[(nt + 2) * 64 + 32 + lane];
            } else {
                c1a = Kn[(nt - 6) * 64 + lane];
                c1b = Kn[(nt - 6) * 64 + 32 + lane];
            }
            mma16(o[nt], Ph[0], ba.x, ba.y);  mma16(o[nt], Pl[0], ba.x, ba.y);
            mma16(o[nt], Ph[1], ba.z, ba.w);  mma16(o[nt], Pl[1], ba.z, ba.w);
            mma16(o[nt], Ph[2], bb.x, bb.y);  mma16(o[nt], Pl[2], bb.x, bb.y);
            mma16(o[nt], Ph[3], bb.z, bb.w);  mma16(o[nt], Pl[3], bb.z, bb.w);
        }

        blk = nxt;
    }

    // ---- normalize and write (l is per-row, already warp-consistent) ------
    const float i0 = 1.f / l0;
    const float i1 = 1.f / l1;
    float* ob = Out + t * 1024;
    #pragma unroll
    for (int nt = 0; nt < 8; ++nt) {
        *(float2*)(ob + gid * 64 + 8 * nt + 2 * qid) =
            make_float2(o[nt][0] * i0, o[nt][1] * i0);
        *(float2*)(ob + (gid + 8) * 64 + 8 * nt + 2 * qid) =
            make_float2(o[nt][2] * i1, o[nt][3] * i1);
    }
}

extern "C" void kernel_launch(void* const* d_in, const int* in_sizes, int n_in,
                              void* d_out, int out_size) {
    const float* Q  = (const float*)d_in[0];
    const float* K  = (const float*)d_in[1];
    const float* V  = (const float*)d_in[2];
    const int*   BI = (const int*)d_in[3];
    pack_kernel<<<64, 256>>>(K, V);
    nsa6<<<TT, 32>>>(Q, BI, (float*)d_out);
}

// round 7
// speedup vs baseline: 9.1325x; 1.2019x over previous
#include <cuda_runtime.h>
#include <cuda_fp16.h>
#include <math.h>

#define TT 2048

// Fragment-ordered plain-fp16 K and V(transposed):
// [blk][nt][p][lane] -> int4 {b0(2p),b1(2p),b0(2p+1),b1(2p+1)} (fp16x2 each)
__device__ int4 g_K[32 * 8 * 2 * 32];   // 256 KB
__device__ int4 g_V[32 * 8 * 2 * 32];   // 256 KB

__device__ __forceinline__ unsigned h2u(float x, float y) {
    __half2 h = __floats2half2_rn(x, y);
    return *(unsigned*)&h;
}

__global__ void __launch_bounds__(256) pack_kernel(
    const float* __restrict__ K, const float* __restrict__ V)
{
    const int i    = blockIdx.x * 256 + threadIdx.x;   // 0..16383
    const int lane = i & 31;
    const int p    = (i >> 5) & 1;
    const int nt   = (i >> 6) & 7;
    const int blk  = i >> 9;
    const int gid  = lane >> 2, qid = lane & 3;
    const int r    = 8 * nt + gid;
    const int c0   = 32 * p + 2 * qid;
    const int c1   = c0 + 16;

    const float* Kb = K + blk * 4096;
    const float* Vb = V + blk * 4096;

    g_K[i] = make_int4(
        (int)h2u(Kb[r * 64 + c0],      Kb[r * 64 + c0 + 1]),
        (int)h2u(Kb[r * 64 + c0 + 8],  Kb[r * 64 + c0 + 9]),
        (int)h2u(Kb[r * 64 + c1],      Kb[r * 64 + c1 + 1]),
        (int)h2u(Kb[r * 64 + c1 + 8],  Kb[r * 64 + c1 + 9]));

    g_V[i] = make_int4(
        (int)h2u(Vb[c0 * 64 + r],       Vb[(c0 + 1) * 64 + r]),
        (int)h2u(Vb[(c0 + 8) * 64 + r], Vb[(c0 + 9) * 64 + r]),
        (int)h2u(Vb[c1 * 64 + r],       Vb[(c1 + 1) * 64 + r]),
        (int)h2u(Vb[(c1 + 8) * 64 + r], Vb[(c1 + 9) * 64 + r]));
}

__device__ __forceinline__ void mma16(float c[4], const int4 a, int b0, int b1) {
    asm volatile(
        "mma.sync.aligned.m16n8k16.row.col.f32.f16.f16.f32 "
        "{%0,%1,%2,%3}, {%4,%5,%6,%7}, {%8,%9}, {%0,%1,%2,%3};\n"
        : "+f"(c[0]), "+f"(c[1]), "+f"(c[2]), "+f"(c[3])
        : "r"(a.x), "r"(a.y), "r"(a.z), "r"(a.w), "r"(b0), "r"(b1));
}

// Two warps per token (split-KV): warp w handles selected blocks [8w, 8w+8).
// Scores kept in log2 domain (Q pre-scaled by 0.125*log2e) -> exp2f softmax.
// P stays plain fp16 (single-term PV); Q stays 2-term hi+lo.
// Per-lane partial l, reduced once at the end. Split-softmax merge in SMEM.
__global__ void __launch_bounds__(64, 8) nsa7(
    const float* __restrict__ Q,   // [T,16,64]
    const int*   __restrict__ BI,  // [T,16]
    float* __restrict__ Out)       // [T,16,64]
{
    __shared__ float sm_m[2][16];
    __shared__ float sm_l[2][16];
    __shared__ float sm_o[16 * 66];

    const int t    = blockIdx.x;
    const int w    = threadIdx.x >> 5;
    const int lane = threadIdx.x & 31;
    const int gid  = lane >> 2;
    const int qid  = lane & 3;

    // ---- Q A-fragments (scaled by 0.125*log2e, fp16 hi+lo), in registers --
    int4 Qh[4], Ql[4];
    {
        const float SC = 0.18033688011112042f;   // 0.125 * log2(e)
        const float* Qp = Q + t * 1024;
        #pragma unroll
        for (int ks = 0; ks < 4; ++ks) {
            const int c0 = 16 * ks + 2 * qid;
            float2 x0 = *(const float2*)(Qp + gid * 64 + c0);
            float2 x1 = *(const float2*)(Qp + (gid + 8) * 64 + c0);
            float2 x2 = *(const float2*)(Qp + gid * 64 + c0 + 8);
            float2 x3 = *(const float2*)(Qp + (gid + 8) * 64 + c0 + 8);
            x0.x *= SC; x0.y *= SC; x1.x *= SC; x1.y *= SC;
            x2.x *= SC; x2.y *= SC; x3.x *= SC; x3.y *= SC;
            __half2 h0 = __floats2half2_rn(x0.x, x0.y);
            __half2 h1 = __floats2half2_rn(x1.x, x1.y);
            __half2 hv = __floats2half2_rn(x2.x, x2.y);
            __half2 h3 = __floats2half2_rn(x3.x, x3.y);
            Qh[ks] = make_int4(*(int*)&h0, *(int*)&h1, *(int*)&hv, *(int*)&h3);
            Ql[ks] = make_int4(
                (int)h2u(x0.x - __low2float(h0), x0.y - __high2float(h0)),
                (int)h2u(x1.x - __low2float(h1), x1.y - __high2float(h1)),
                (int)h2u(x2.x - __low2float(hv), x2.y - __high2float(hv)),
                (int)h2u(x3.x - __low2float(h3), x3.y - __high2float(h3)));
        }
    }

    float o[8][4];
    #pragma unroll
    for (int nt = 0; nt < 8; ++nt)
        o[nt][0] = o[nt][1] = o[nt][2] = o[nt][3] = 0.f;
    float m0 = -INFINITY, m1 = -INFINITY, l0 = 0.f, l1 = 0.f;

    const int* bip = BI + t * 16 + w * 8;
    int blk = __ldg(bip);

    // Rotating stream buffer (2-tile lookahead across phases).
    int4 c0a, c0b, c1a, c1b;
    {
        const int4* KB = g_K + (size_t)blk * 512;
        c0a = KB[lane];       c0b = KB[32 + lane];
        c1a = KB[64 + lane];  c1b = KB[96 + lane];
    }

    #pragma unroll 1
    for (int s = 0; s < 8; ++s) {
        const int blkc = blk;
        const int nxt  = (s < 7) ? __ldg(bip + s + 1) : 0;
        const int4* Kb = g_K + (size_t)blkc * 512;
        const int4* Vb = g_V + (size_t)blkc * 512;
        const int4* Kn = g_K + (size_t)nxt * 512;

        // ---- QK: 8 n-tiles, 2-term fp16 Q x plain fp16 K ------------------
        float sc[8][4];
        #pragma unroll
        for (int nt = 0; nt < 8; ++nt) {
            const int4 ba = c0a, bb = c0b;
            c0a = c1a; c0b = c1b;
            if (nt < 6) {
                c1a = Kb[(nt + 2) * 64 + lane];
                c1b = Kb[(nt + 2) * 64 + 32 + lane];
            } else {
                c1a = Vb[(nt - 6) * 64 + lane];
                c1b = Vb[(nt - 6) * 64 + 32 + lane];
            }
            float a[4] = {0.f, 0.f, 0.f, 0.f};
            mma16(a, Qh[0], ba.x, ba.y);  mma16(a, Ql[0], ba.x, ba.y);
            mma16(a, Qh[1], ba.z, ba.w);  mma16(a, Ql[1], ba.z, ba.w);
            mma16(a, Qh[2], bb.x, bb.y);  mma16(a, Ql[2], bb.x, bb.y);
            mma16(a, Qh[3], bb.z, bb.w);  mma16(a, Ql[3], bb.z, bb.w);
            const int kp = blkc * 64 + 8 * nt + 2 * qid;
            sc[nt][0] = (kp     <= t) ? a[0] : -INFINITY;
            sc[nt][1] = (kp + 1 <= t) ? a[1] : -INFINITY;
            sc[nt][2] = (kp     <= t) ? a[2] : -INFINITY;
            sc[nt][3] = (kp + 1 <= t) ? a[3] : -INFINITY;
        }

        // ---- softmax in log2 domain ---------------------------------------
        float bm0 = m0, bm1 = m1;
        #pragma unroll
        for (int nt = 0; nt < 8; ++nt) {
            bm0 = fmaxf(bm0, fmaxf(sc[nt][0], sc[nt][1]));
            bm1 = fmaxf(bm1, fmaxf(sc[nt][2], sc[nt][3]));
        }
        bm0 = fmaxf(bm0, __shfl_xor_sync(0xffffffffu, bm0, 1));
        bm0 = fmaxf(bm0, __shfl_xor_sync(0xffffffffu, bm0, 2));
        bm1 = fmaxf(bm1, __shfl_xor_sync(0xffffffffu, bm1, 1));
        bm1 = fmaxf(bm1, __shfl_xor_sync(0xffffffffu, bm1, 2));
        const float s0 = (bm0 == -INFINITY) ? 0.f : bm0;
        const float s1 = (bm1 == -INFINITY) ? 0.f : bm1;
        const float corr0 = exp2f(m0 - s0);
        const float corr1 = exp2f(m1 - s1);
        m0 = bm0; m1 = bm1;

        // ---- exp2 -> plain fp16 P A-fragments; per-lane partial l ---------
        int4 Ph[4];
        float pl0 = 0.f, pl1 = 0.f;
        #pragma unroll
        for (int p = 0; p < 4; ++p) {
            unsigned hb[4];
            #pragma unroll
            for (int j = 0; j < 2; ++j) {
                const int nt = 2 * p + j;
                const float e0 = exp2f(sc[nt][0] - s0);
                const float e1 = exp2f(sc[nt][1] - s0);
                const float e2 = exp2f(sc[nt][2] - s1);
                const float e3 = exp2f(sc[nt][3] - s1);
                pl0 += e0 + e1;
                pl1 += e2 + e3;
                hb[2 * j]     = h2u(e0, e1);
                hb[2 * j + 1] = h2u(e2, e3);
            }
            Ph[p] = make_int4((int)hb[0], (int)hb[1], (int)hb[2], (int)hb[3]);
        }
        l0 = l0 * corr0 + pl0;     // lane-partial; reduced after the loop
        l1 = l1 * corr1 + pl1;
        #pragma unroll
        for (int nt = 0; nt < 8; ++nt) {
            o[nt][0] *= corr0; o[nt][1] *= corr0;
            o[nt][2] *= corr1; o[nt][3] *= corr1;
        }

        // ---- PV: 8 d-tiles, single-term P ---------------------------------
        #pragma unroll
        for (int nt = 0; nt < 8; ++nt) {
            const int4 ba = c0a, bb = c0b;
            c0a = c1a; c0b = c1b;
            if (nt < 6) {
                c1a = Vb[(nt + 2) * 64 + lane];
                c1b = Vb[(nt + 2) * 64 + 32 + lane];
            } else {
                c1a = Kn[(nt - 6) * 64 + lane];
                c1b = Kn[(nt - 6) * 64 + 32 + lane];
            }
            mma16(o[nt], Ph[0], ba.x, ba.y);
            mma16(o[nt], Ph[1], ba.z, ba.w);
            mma16(o[nt], Ph[2], bb.x, bb.y);
            mma16(o[nt], Ph[3], bb.z, bb.w);
        }

        blk = nxt;
    }

    // ---- finish per-row l (reduce over the quad) --------------------------
    l0 += __shfl_xor_sync(0xffffffffu, l0, 1);
    l0 += __shfl_xor_sync(0xffffffffu, l0, 2);
    l1 += __shfl_xor_sync(0xffffffffu, l1, 1);
    l1 += __shfl_xor_sync(0xffffffffu, l1, 2);
    if (qid == 0) {
        sm_m[w][gid]     = m0;  sm_m[w][gid + 8] = m1;
        sm_l[w][gid]     = l0;  sm_l[w][gid + 8] = l1;
    }
    __syncthreads();

    // ---- split-softmax merge ----------------------------------------------
    const float M0 = fmaxf(sm_m[0][gid],     sm_m[1][gid]);
    const float M1 = fmaxf(sm_m[0][gid + 8], sm_m[1][gid + 8]);
    const float a0 = exp2f(m0 - M0);   // own warp's alpha
    const float a1 = exp2f(m1 - M1);

    if (w == 0) {
        #pragma unroll
        for (int nt = 0; nt < 8; ++nt) {
            *(float2*)(sm_o + gid * 66 + 8 * nt + 2 * qid) =
                make_float2(o[nt][0] * a0, o[nt][1] * a0);
            *(float2*)(sm_o + (gid + 8) * 66 + 8 * nt + 2 * qid) =
                make_float2(o[nt][2] * a1, o[nt][3] * a1);
        }
    }
    __syncthreads();
    if (w == 1) {
        const float L0 = exp2f(sm_m[0][gid] - M0) * sm_l[0][gid]
                       + exp2f(sm_m[1][gid] - M0) * sm_l[1][gid];
        const float L1 = exp2f(sm_m[0][gid + 8] - M1) * sm_l[0][gid + 8]
                       + exp2f(sm_m[1][gid + 8] - M1) * sm_l[1][gid + 8];
        const float i0 = 1.f / L0;
        const float i1 = 1.f / L1;
        float* ob = Out + t * 1024;
        #pragma unroll
        for (int nt = 0; nt < 8; ++nt) {
            float2 u0 = *(float2*)(sm_o + gid * 66 + 8 * nt + 2 * qid);
            float2 u1 = *(float2*)(sm_o + (gid + 8) * 66 + 8 * nt + 2 * qid);
            *(float2*)(ob + gid * 64 + 8 * nt + 2 * qid) =
                make_float2((u0.x + o[nt][0] * a0) * i0,
                            (u0.y + o[nt][1] * a0) * i0);
            *(float2*)(ob + (gid + 8) * 64 + 8 * nt + 2 * qid) =
                make_float2((u1.x + o[nt][2] * a1) * i1,
                            (u1.y + o[nt][3] * a1) * i1);
        }
    }
}

extern "C" void kernel_launch(void* const* d_in, const int* in_sizes, int n_in,
                              void* d_out, int out_size) {
    const float* Q  = (const float*)d_in[0];
    const float* K  = (const float*)d_in[1];
    const float* V  = (const float*)d_in[2];
    const int*   BI = (const int*)d_in[3];
    pack_kernel<<<64, 256>>>(K, V);
    nsa7<<<TT, 64>>>(Q, BI, (float*)d_out);
}

// round 8
// speedup vs baseline: 10.2617x; 1.1236x over previous
#include <cuda_runtime.h>
#include <cuda_fp16.h>
#include <math.h>

#define TT 2048

// Fragment-ordered plain-fp16 K and V(transposed):
// [blk][nt][p][lane] -> int4 {b0(2p),b1(2p),b0(2p+1),b1(2p+1)} (fp16x2 each)
__device__ int4 g_K[32 * 8 * 2 * 32];   // 256 KB
__device__ int4 g_V[32 * 8 * 2 * 32];   // 256 KB

__device__ __forceinline__ unsigned h2u(float x, float y) {
    __half2 h = __floats2half2_rn(x, y);
    return *(unsigned*)&h;
}

__global__ void __launch_bounds__(256) pack_kernel(
    const float* __restrict__ K, const float* __restrict__ V)
{
    const int i    = blockIdx.x * 256 + threadIdx.x;   // 0..16383
    const int lane = i & 31;
    const int p    = (i >> 5) & 1;
    const int nt   = (i >> 6) & 7;
    const int blk  = i >> 9;
    const int gid  = lane >> 2, qid = lane & 3;
    const int r    = 8 * nt + gid;
    const int c0   = 32 * p + 2 * qid;
    const int c1   = c0 + 16;

    const float* Kb = K + blk * 4096;
    const float* Vb = V + blk * 4096;

    g_K[i] = make_int4(
        (int)h2u(Kb[r * 64 + c0],      Kb[r * 64 + c0 + 1]),
        (int)h2u(Kb[r * 64 + c0 + 8],  Kb[r * 64 + c0 + 9]),
        (int)h2u(Kb[r * 64 + c1],      Kb[r * 64 + c1 + 1]),
        (int)h2u(Kb[r * 64 + c1 + 8],  Kb[r * 64 + c1 + 9]));

    g_V[i] = make_int4(
        (int)h2u(Vb[c0 * 64 + r],       Vb[(c0 + 1) * 64 + r]),
        (int)h2u(Vb[(c0 + 8) * 64 + r], Vb[(c0 + 9) * 64 + r]),
        (int)h2u(Vb[c1 * 64 + r],       Vb[(c1 + 1) * 64 + r]),
        (int)h2u(Vb[(c1 + 8) * 64 + r], Vb[(c1 + 9) * 64 + r]));
}

__device__ __forceinline__ void mma16(float c[4], const int4 a, int b0, int b1) {
    asm volatile(
        "mma.sync.aligned.m16n8k16.row.col.f32.f16.f16.f32 "
        "{%0,%1,%2,%3}, {%4,%5,%6,%7}, {%8,%9}, {%0,%1,%2,%3};\n"
        : "+f"(c[0]), "+f"(c[1]), "+f"(c[2]), "+f"(c[3])
        : "r"(a.x), "r"(a.y), "r"(a.z), "r"(a.w), "r"(b0), "r"(b1));
}

#define ONES 0x3C003C00   // fp16x2 (1.0, 1.0)

// Two warps per token (split-KV, 8 blocks each). Lazy-reference softmax:
// exp uses the PREVIOUS blocks' max as reference (no shfl on critical path);
// the running max / rescale happen at block end, off the critical path.
// l is computed by an extra MMA against an all-ones B (fp32, quad-uniform,
// exactly consistent with the fp16 P used in PV). Q is plain fp16 (1-term).
__global__ void __launch_bounds__(64, 10) nsa8(
    const float* __restrict__ Q,   // [T,16,64]
    const int*   __restrict__ BI,  // [T,16]
    float* __restrict__ Out)       // [T,16,64]
{
    __shared__ float sm_m[2][16];
    __shared__ float sm_l[2][16];
    __shared__ float sm_o[16 * 66];

    const int t    = blockIdx.x;
    const int w    = threadIdx.x >> 5;
    const int lane = threadIdx.x & 31;
    const int gid  = lane >> 2;
    const int qid  = lane & 3;

    // ---- Q A-fragments (scaled by 0.125*log2e), plain fp16, in regs -------
    int4 Qh[4];
    {
        const float SC = 0.18033688011112042f;   // 0.125 * log2(e)
        const float* Qp = Q + t * 1024;
        #pragma unroll
        for (int ks = 0; ks < 4; ++ks) {
            const int c0 = 16 * ks + 2 * qid;
            float2 x0 = *(const float2*)(Qp + gid * 64 + c0);
            float2 x1 = *(const float2*)(Qp + (gid + 8) * 64 + c0);
            float2 x2 = *(const float2*)(Qp + gid * 64 + c0 + 8);
            float2 x3 = *(const float2*)(Qp + (gid + 8) * 64 + c0 + 8);
            Qh[ks] = make_int4(
                (int)h2u(x0.x * SC, x0.y * SC),
                (int)h2u(x1.x * SC, x1.y * SC),
                (int)h2u(x2.x * SC, x2.y * SC),
                (int)h2u(x3.x * SC, x3.y * SC));
        }
    }

    float o[8][4];
    #pragma unroll
    for (int dt = 0; dt < 8; ++dt)
        o[dt][0] = o[dt][1] = o[dt][2] = o[dt][3] = 0.f;
    float la[4] = {0.f, 0.f, 0.f, 0.f};
    float m0 = -INFINITY, m1 = -INFINITY;
    float ref0 = 0.f, ref1 = 0.f;          // finite exp reference

    const int* bip = BI + t * 16 + w * 8;
    int blk = __ldg(bip);

    #pragma unroll 1
    for (int s = 0; s < 8; ++s) {
        const int blkc = blk;
        const int nxt  = (s < 7) ? __ldg(bip + s + 1) : 0;
        const int4* Kb = g_K + (size_t)blkc * 512;
        const int4* Vb = g_V + (size_t)blkc * 512;

        float bm0 = m0, bm1 = m1;
        int4 Ph[2];

        // ================= half 1: n-tiles 0..3, PV k-steps 0,1 ============
        {
            float sc[4][4];
            #pragma unroll
            for (int nt = 0; nt < 4; ++nt) {
                const int4 ba = Kb[nt * 64 + lane];
                const int4 bb = Kb[nt * 64 + 32 + lane];
                float a[4] = {0.f, 0.f, 0.f, 0.f};
                mma16(a, Qh[0], ba.x, ba.y);
                mma16(a, Qh[1], ba.z, ba.w);
                mma16(a, Qh[2], bb.x, bb.y);
                mma16(a, Qh[3], bb.z, bb.w);
                const int kp = blkc * 64 + 8 * nt + 2 * qid;
                sc[nt][0] = (kp     <= t) ? a[0] : -INFINITY;
                sc[nt][1] = (kp + 1 <= t) ? a[1] : -INFINITY;
                sc[nt][2] = (kp     <= t) ? a[2] : -INFINITY;
                sc[nt][3] = (kp + 1 <= t) ? a[3] : -INFINITY;
            }
            #pragma unroll
            for (int nt = 0; nt < 4; ++nt) {
                bm0 = fmaxf(bm0, fmaxf(sc[nt][0], sc[nt][1]));
                bm1 = fmaxf(bm1, fmaxf(sc[nt][2], sc[nt][3]));
            }
            #pragma unroll
            for (int p = 0; p < 2; ++p) {
                unsigned hb[4];
                #pragma unroll
                for (int j = 0; j < 2; ++j) {
                    const int nt = 2 * p + j;
                    __half2 e01 = h2exp2(__floats2half2_rn(sc[nt][0] - ref0,
                                                           sc[nt][1] - ref0));
                    __half2 e23 = h2exp2(__floats2half2_rn(sc[nt][2] - ref1,
                                                           sc[nt][3] - ref1));
                    hb[2 * j]     = *(unsigned*)&e01;
                    hb[2 * j + 1] = *(unsigned*)&e23;
                }
                Ph[p] = make_int4((int)hb[0], (int)hb[1], (int)hb[2], (int)hb[3]);
            }
            #pragma unroll
            for (int dt = 0; dt < 8; ++dt) {
                const int4 v = Vb[dt * 64 + lane];        // k-steps 0,1
                mma16(o[dt], Ph[0], v.x, v.y);
                mma16(o[dt], Ph[1], v.z, v.w);
            }
            mma16(la, Ph[0], ONES, ONES);
            mma16(la, Ph[1], ONES, ONES);
        }

        // ================= half 2: n-tiles 4..7, PV k-steps 2,3 ============
        {
            float sc[4][4];
            #pragma unroll
            for (int nt = 0; nt < 4; ++nt) {
                const int4 ba = Kb[(nt + 4) * 64 + lane];
                const int4 bb = Kb[(nt + 4) * 64 + 32 + lane];
                float a[4] = {0.f, 0.f, 0.f, 0.f};
                mma16(a, Qh[0], ba.x, ba.y);
                mma16(a, Qh[1], ba.z, ba.w);
                mma16(a, Qh[2], bb.x, bb.y);
                mma16(a, Qh[3], bb.z, bb.w);
                const int kp = blkc * 64 + 8 * (nt + 4) + 2 * qid;
                sc[nt][0] = (kp     <= t) ? a[0] : -INFINITY;
                sc[nt][1] = (kp + 1 <= t) ? a[1] : -INFINITY;
                sc[nt][2] = (kp     <= t) ? a[2] : -INFINITY;
                sc[nt][3] = (kp + 1 <= t) ? a[3] : -INFINITY;
            }
            #pragma unroll
            for (int nt = 0; nt < 4; ++nt) {
                bm0 = fmaxf(bm0, fmaxf(sc[nt][0], sc[nt][1]));
                bm1 = fmaxf(bm1, fmaxf(sc[nt][2], sc[nt][3]));
            }
            #pragma unroll
            for (int p = 0; p < 2; ++p) {
                unsigned hb[4];
                #pragma unroll
                for (int j = 0; j < 2; ++j) {
                    const int nt = 2 * p + j;
                    __half2 e01 = h2exp2(__floats2half2_rn(sc[nt][0] - ref0,
                                                           sc[nt][1] - ref0));
                    __half2 e23 = h2exp2(__floats2half2_rn(sc[nt][2] - ref1,
                                                           sc[nt][3] - ref1));
                    hb[2 * j]     = *(unsigned*)&e01;
                    hb[2 * j + 1] = *(unsigned*)&e23;
                }
                Ph[p] = make_int4((int)hb[0], (int)hb[1], (int)hb[2], (int)hb[3]);
            }
            #pragma unroll
            for (int dt = 0; dt < 8; ++dt) {
                const int4 v = Vb[dt * 64 + 32 + lane];   // k-steps 2,3
                mma16(o[dt], Ph[0], v.x, v.y);
                mma16(o[dt], Ph[1], v.z, v.w);
            }
            mma16(la, Ph[0], ONES, ONES);
            mma16(la, Ph[1], ONES, ONES);
        }

        // ---- block end: update max / reference, rescale (off exp path) ----
        bm0 = fmaxf(bm0, __shfl_xor_sync(0xffffffffu, bm0, 1));
        bm0 = fmaxf(bm0, __shfl_xor_sync(0xffffffffu, bm0, 2));
        bm1 = fmaxf(bm1, __shfl_xor_sync(0xffffffffu, bm1, 1));
        bm1 = fmaxf(bm1, __shfl_xor_sync(0xffffffffu, bm1, 2));
        const float nr0 = (bm0 == -INFINITY) ? 0.f : bm0;
        const float nr1 = (bm1 == -INFINITY) ? 0.f : bm1;
        const float c0 = exp2f(ref0 - nr0);
        const float c1 = exp2f(ref1 - nr1);
        #pragma unroll
        for (int dt = 0; dt < 8; ++dt) {
            o[dt][0] *= c0; o[dt][1] *= c0;
            o[dt][2] *= c1; o[dt][3] *= c1;
        }
        la[0] *= c0; la[1] *= c0; la[2] *= c1; la[3] *= c1;
        m0 = bm0; m1 = bm1; ref0 = nr0; ref1 = nr1;
        blk = nxt;
    }

    // ---- split-softmax merge (la[0]/la[2] are quad-uniform row sums) ------
    if (qid == 0) {
        sm_m[w][gid] = m0;  sm_m[w][gid + 8] = m1;
        sm_l[w][gid] = la[0]; sm_l[w][gid + 8] = la[2];
    }
    __syncthreads();

    const float M0 = fmaxf(sm_m[0][gid],     sm_m[1][gid]);      // finite
    const float M1 = fmaxf(sm_m[0][gid + 8], sm_m[1][gid + 8]);  // finite
    const float a0 = exp2f(ref0 - M0);   // own warp's alpha (ref = finite(m))
    const float a1 = exp2f(ref1 - M1);

    if (w == 0) {
        #pragma unroll
        for (int dt = 0; dt < 8; ++dt) {
            *(float2*)(sm_o + gid * 66 + 8 * dt + 2 * qid) =
                make_float2(o[dt][0] * a0, o[dt][1] * a0);
            *(float2*)(sm_o + (gid + 8) * 66 + 8 * dt + 2 * qid) =
                make_float2(o[dt][2] * a1, o[dt][3] * a1);
        }
    }
    __syncthreads();
    if (w == 1) {
        const float rf00 = (sm_m[0][gid] == -INFINITY)     ? 0.f : sm_m[0][gid];
        const float rf10 = (sm_m[1][gid] == -INFINITY)     ? 0.f : sm_m[1][gid];
        const float rf01 = (sm_m[0][gid + 8] == -INFINITY) ? 0.f : sm_m[0][gid + 8];
        const float rf11 = (sm_m[1][gid + 8] == -INFINITY) ? 0.f : sm_m[1][gid + 8];
        const float L0 = exp2f(rf00 - M0) * sm_l[0][gid]
                       + exp2f(rf10 - M0) * sm_l[1][gid];
        const float L1 = exp2f(rf01 - M1) * sm_l[0][gid + 8]
                       + exp2f(rf11 - M1) * sm_l[1][gid + 8];
        const float i0 = 1.f / L0;
        const float i1 = 1.f / L1;
        float* ob = Out + t * 1024;
        #pragma unroll
        for (int dt = 0; dt < 8; ++dt) {
            float2 u0 = *(float2*)(sm_o + gid * 66 + 8 * dt + 2 * qid);
            float2 u1 = *(float2*)(sm_o + (gid + 8) * 66 + 8 * dt + 2 * qid);
            *(float2*)(ob + gid * 64 + 8 * dt + 2 * qid) =
                make_float2((u0.x + o[dt][0] * a0) * i0,
                            (u0.y + o[dt][1] * a0) * i0);
            *(float2*)(ob + (gid + 8) * 64 + 8 * dt + 2 * qid) =
                make_float2((u1.x + o[dt][2] * a1) * i1,
                            (u1.y + o[dt][3] * a1) * i1);
        }
    }
}

extern "C" void kernel_launch(void* const* d_in, const int* in_sizes, int n_in,
                              void* d_out, int out_size) {
    const float* Q  = (const float*)d_in[0];
    const float* K  = (const float*)d_in[1];
    const float* V  = (const float*)d_in[2];
    const int*   BI = (const int*)d_in[3];
    pack_kernel<<<64, 256>>>(K, V);
    nsa8<<<TT, 64>>>(Q, BI, (float*)d_out);
}

// round 9
// speedup vs baseline: 12.4154x; 1.2099x over previous
#include <cuda_runtime.h>
#include <cuda_fp16.h>
#include <math.h>

#define TT 2048

// Fragment-ordered plain-fp16 K and V(transposed):
// [blk][nt][p][lane] -> int4 {b0(2p),b1(2p),b0(2p+1),b1(2p+1)} (fp16x2 each)
__device__ int4 g_K[32 * 8 * 2 * 32];   // 256 KB
__device__ int4 g_V[32 * 8 * 2 * 32];   // 256 KB

__device__ __forceinline__ unsigned h2u(float x, float y) {
    __half2 h = __floats2half2_rn(x, y);
    return *(unsigned*)&h;
}

__global__ void __launch_bounds__(256) pack_kernel(
    const float* __restrict__ K, const float* __restrict__ V)
{
    const int i    = blockIdx.x * 256 + threadIdx.x;   // 0..16383
    const int lane = i & 31;
    const int p    = (i >> 5) & 1;
    const int nt   = (i >> 6) & 7;
    const int blk  = i >> 9;
    const int gid  = lane >> 2, qid = lane & 3;
    const int r    = 8 * nt + gid;
    const int c0   = 32 * p + 2 * qid;
    const int c1   = c0 + 16;

    const float* Kb = K + blk * 4096;
    const float* Vb = V + blk * 4096;

    g_K[i] = make_int4(
        (int)h2u(Kb[r * 64 + c0],      Kb[r * 64 + c0 + 1]),
        (int)h2u(Kb[r * 64 + c0 + 8],  Kb[r * 64 + c0 + 9]),
        (int)h2u(Kb[r * 64 + c1],      Kb[r * 64 + c1 + 1]),
        (int)h2u(Kb[r * 64 + c1 + 8],  Kb[r * 64 + c1 + 9]));

    g_V[i] = make_int4(
        (int)h2u(Vb[c0 * 64 + r],       Vb[(c0 + 1) * 64 + r]),
        (int)h2u(Vb[(c0 + 8) * 64 + r], Vb[(c0 + 9) * 64 + r]),
        (int)h2u(Vb[c1 * 64 + r],       Vb[(c1 + 1) * 64 + r]),
        (int)h2u(Vb[(c1 + 8) * 64 + r], Vb[(c1 + 9) * 64 + r]));
}

__device__ __forceinline__ void mma16(float c[4], const int4 a, int b0, int b1) {
    asm volatile(
        "mma.sync.aligned.m16n8k16.row.col.f32.f16.f16.f32 "
        "{%0,%1,%2,%3}, {%4,%5,%6,%7}, {%8,%9}, {%0,%1,%2,%3};\n"
        : "+f"(c[0]), "+f"(c[1]), "+f"(c[2]), "+f"(c[3])
        : "r"(a.x), "r"(a.y), "r"(a.z), "r"(a.w), "r"(b0), "r"(b1));
}

__device__ __forceinline__ void cp16(int4* smem_dst, const int4* gmem_src) {
    unsigned sa = (unsigned)__cvta_generic_to_shared(smem_dst);
    asm volatile("cp.async.cg.shared.global [%0], [%1], 16;\n"
                 :: "r"(sa), "l"(gmem_src));
}
#define CP_COMMIT() asm volatile("cp.async.commit_group;\n" ::: "memory")
#define CP_WAIT2()  asm volatile("cp.async.wait_group 2;\n" ::: "memory")

#define ONES 0x3C003C00   // fp16x2 (1.0, 1.0)

__device__ __forceinline__ int p3(int x) { return (x >= 3) ? x - 3 : x; }

// Two warps per token (split-KV, 8 blocks each). Lazy-reference softmax (R8).
// K streams through a per-warp 3-slot SMEM ring via cp.async, issued two
// half-phases ahead (wait_group 2). Each lane LDS-reads only entries it cp'd
// itself -> per-thread wait suffices, no barriers. V is LDG'd into registers
// at half-start, before the K wait, consumed in PV.
__global__ void __launch_bounds__(64, 8) nsa9(
    const float* __restrict__ Q,   // [T,16,64]
    const int*   __restrict__ BI,  // [T,16]
    float* __restrict__ Out)       // [T,16,64]
{
    __shared__ int4  sK[2 * 3 * 256];    // 2 warps x 3 slots x 4KB
    __shared__ float sm_m[2][16];
    __shared__ float sm_l[2][16];
    __shared__ float sm_o[16 * 66];
    #define KSLOT(wi, si, ei) sK[(wi) * 768 + (si) * 256 + (ei)]

    const int t    = blockIdx.x;
    const int w    = threadIdx.x >> 5;
    const int lane = threadIdx.x & 31;
    const int gid  = lane >> 2;
    const int qid  = lane & 3;

    // ---- Q A-fragments (scaled by 0.125*log2e), plain fp16, in regs -------
    int4 Qh[4];
    {
        const float SC = 0.18033688011112042f;   // 0.125 * log2(e)
        const float* Qp = Q + t * 1024;
        #pragma unroll
        for (int ks = 0; ks < 4; ++ks) {
            const int c0 = 16 * ks + 2 * qid;
            float2 x0 = *(const float2*)(Qp + gid * 64 + c0);
            float2 x1 = *(const float2*)(Qp + (gid + 8) * 64 + c0);
            float2 x2 = *(const float2*)(Qp + gid * 64 + c0 + 8);
            float2 x3 = *(const float2*)(Qp + (gid + 8) * 64 + c0 + 8);
            Qh[ks] = make_int4(
                (int)h2u(x0.x * SC, x0.y * SC),
                (int)h2u(x1.x * SC, x1.y * SC),
                (int)h2u(x2.x * SC, x2.y * SC),
                (int)h2u(x3.x * SC, x3.y * SC));
        }
    }

    float o[8][4];
    #pragma unroll
    for (int dt = 0; dt < 8; ++dt)
        o[dt][0] = o[dt][1] = o[dt][2] = o[dt][3] = 0.f;
    float la[4] = {0.f, 0.f, 0.f, 0.f};
    float m0 = -INFINITY, m1 = -INFINITY;
    float ref0 = 0.f, ref1 = 0.f;

    const int* bip = BI + t * 16 + w * 8;
    int blk = __ldg(bip);

    // ---- preload: (blk0, half0) -> slot0, (blk0, half1) -> slot1 ----------
    {
        const int4* srcb = g_K + (size_t)blk * 512;
        #pragma unroll
        for (int j = 0; j < 8; ++j)
            cp16(&KSLOT(w, 0, j * 32 + lane), srcb + j * 32 + lane);
        CP_COMMIT();
        #pragma unroll
        for (int j = 0; j < 8; ++j)
            cp16(&KSLOT(w, 1, j * 32 + lane), srcb + 256 + j * 32 + lane);
        CP_COMMIT();
    }

    int cslot = 0;

    #pragma unroll 1
    for (int s = 0; s < 8; ++s) {
        const int blkc = blk;
        const int nxt  = (s < 7) ? __ldg(bip + s + 1) : 0;
        const int4* Vb = g_V + (size_t)blkc * 512;
        const int4* Kn = g_K + (size_t)nxt * 512;

        float bm0 = m0, bm1 = m1;
        int4 Ph[2];

        #pragma unroll
        for (int h = 0; h < 2; ++h) {
            // -- issue next block's same-half K into slot cslot+2 -----------
            {
                const int4* src = Kn + h * 256;
                const int tslot = p3(cslot + 2);
                #pragma unroll
                for (int j = 0; j < 8; ++j)
                    cp16(&KSLOT(w, tslot, j * 32 + lane), src + j * 32 + lane);
                CP_COMMIT();
            }
            // -- early V loads for this half --------------------------------
            int4 v[8];
            #pragma unroll
            for (int dt = 0; dt < 8; ++dt)
                v[dt] = Vb[dt * 64 + 32 * h + lane];

            // -- wait for this half's K, then QK ----------------------------
            CP_WAIT2();
            float sc[4][4];
            #pragma unroll
            for (int nt = 0; nt < 4; ++nt) {
                const int4 ba = KSLOT(w, cslot, nt * 64 + lane);
                const int4 bb = KSLOT(w, cslot, nt * 64 + 32 + lane);
                float a[4] = {0.f, 0.f, 0.f, 0.f};
                mma16(a, Qh[0], ba.x, ba.y);
                mma16(a, Qh[1], ba.z, ba.w);
                mma16(a, Qh[2], bb.x, bb.y);
                mma16(a, Qh[3], bb.z, bb.w);
                const int kp = blkc * 64 + 8 * (nt + 4 * h) + 2 * qid;
                sc[nt][0] = (kp     <= t) ? a[0] : -INFINITY;
                sc[nt][1] = (kp + 1 <= t) ? a[1] : -INFINITY;
                sc[nt][2] = (kp     <= t) ? a[2] : -INFINITY;
                sc[nt][3] = (kp + 1 <= t) ? a[3] : -INFINITY;
            }
            #pragma unroll
            for (int nt = 0; nt < 4; ++nt) {
                bm0 = fmaxf(bm0, fmaxf(sc[nt][0], sc[nt][1]));
                bm1 = fmaxf(bm1, fmaxf(sc[nt][2], sc[nt][3]));
            }
            // -- exp (lazy reference) -> P A-fragments ----------------------
            #pragma unroll
            for (int p = 0; p < 2; ++p) {
                unsigned hb[4];
                #pragma unroll
                for (int j = 0; j < 2; ++j) {
                    const int nt = 2 * p + j;
                    __half2 e01 = h2exp2(__floats2half2_rn(sc[nt][0] - ref0,
                                                           sc[nt][1] - ref0));
                    __half2 e23 = h2exp2(__floats2half2_rn(sc[nt][2] - ref1,
                                                           sc[nt][3] - ref1));
                    hb[2 * j]     = *(unsigned*)&e01;
                    hb[2 * j + 1] = *(unsigned*)&e23;
                }
                Ph[p] = make_int4((int)hb[0], (int)hb[1], (int)hb[2], (int)hb[3]);
            }
            // -- PV over this half's k-steps --------------------------------
            #pragma unroll
            for (int dt = 0; dt < 8; ++dt) {
                mma16(o[dt], Ph[0], v[dt].x, v[dt].y);
                mma16(o[dt], Ph[1], v[dt].z, v[dt].w);
            }
            mma16(la, Ph[0], ONES, ONES);
            mma16(la, Ph[1], ONES, ONES);

            cslot = p3(cslot + 1);
        }

        // ---- block end: update max / reference, rescale -------------------
        bm0 = fmaxf(bm0, __shfl_xor_sync(0xffffffffu, bm0, 1));
        bm0 = fmaxf(bm0, __shfl_xor_sync(0xffffffffu, bm0, 2));
        bm1 = fmaxf(bm1, __shfl_xor_sync(0xffffffffu, bm1, 1));
        bm1 = fmaxf(bm1, __shfl_xor_sync(0xffffffffu, bm1, 2));
        const float nr0 = (bm0 == -INFINITY) ? 0.f : bm0;
        const float nr1 = (bm1 == -INFINITY) ? 0.f : bm1;
        const float cr0 = exp2f(ref0 - nr0);
        const float cr1 = exp2f(ref1 - nr1);
        #pragma unroll
        for (int dt = 0; dt < 8; ++dt) {
            o[dt][0] *= cr0; o[dt][1] *= cr0;
            o[dt][2] *= cr1; o[dt][3] *= cr1;
        }
        la[0] *= cr0; la[1] *= cr0; la[2] *= cr1; la[3] *= cr1;
        m0 = bm0; m1 = bm1; ref0 = nr0; ref1 = nr1;
        blk = nxt;
    }

    // ---- split-softmax merge (R8) -----------------------------------------
    if (qid == 0) {
        sm_m[w][gid] = m0;  sm_m[w][gid + 8] = m1;
        sm_l[w][gid] = la[0]; sm_l[w][gid + 8] = la[2];
    }
    __syncthreads();

    const float M0 = fmaxf(sm_m[0][gid],     sm_m[1][gid]);
    const float M1 = fmaxf(sm_m[0][gid + 8], sm_m[1][gid + 8]);
    const float a0 = exp2f(ref0 - M0);
    const float a1 = exp2f(ref1 - M1);

    if (w == 0) {
        #pragma unroll
        for (int dt = 0; dt < 8; ++dt) {
            *(float2*)(sm_o + gid * 66 + 8 * dt + 2 * qid) =
                make_float2(o[dt][0] * a0, o[dt][1] * a0);
            *(float2*)(sm_o + (gid + 8) * 66 + 8 * dt + 2 * qid) =
                make_float2(o[dt][2] * a1, o[dt][3] * a1);
        }
    }
    __syncthreads();
    if (w == 1) {
        const float rf00 = (sm_m[0][gid] == -INFINITY)     ? 0.f : sm_m[0][gid];
        const float rf10 = (sm_m[1][gid] == -INFINITY)     ? 0.f : sm_m[1][gid];
        const float rf01 = (sm_m[0][gid + 8] == -INFINITY) ? 0.f : sm_m[0][gid + 8];
        const float rf11 = (sm_m[1][gid + 8] == -INFINITY) ? 0.f : sm_m[1][gid + 8];
        const float L0 = exp2f(rf00 - M0) * sm_l[0][gid]
                       + exp2f(rf10 - M0) * sm_l[1][gid];
        const float L1 = exp2f(rf01 - M1) * sm_l[0][gid + 8]
                       + exp2f(rf11 - M1) * sm_l[1][gid + 8];
        const float i0 = 1.f / L0;
        const float i1 = 1.f / L1;
        float* ob = Out + t * 1024;
        #pragma unroll
        for (int dt = 0; dt < 8; ++dt) {
            float2 u0 = *(float2*)(sm_o + gid * 66 + 8 * dt + 2 * qid);
            float2 u1 = *(float2*)(sm_o + (gid + 8) * 66 + 8 * dt + 2 * qid);
            *(float2*)(ob + gid * 64 + 8 * dt + 2 * qid) =
                make_float2((u0.x + o[dt][0] * a0) * i0,
                            (u0.y + o[dt][1] * a0) * i0);
            *(float2*)(ob + (gid + 8) * 64 + 8 * dt + 2 * qid) =
                make_float2((u1.x + o[dt][2] * a1) * i1,
                            (u1.y + o[dt][3] * a1) * i1);
        }
    }
}

extern "C" void kernel_launch(void* const* d_in, const int* in_sizes, int n_in,
                              void* d_out, int out_size) {
    const float* Q  = (const float*)d_in[0];
    const float* K  = (const float*)d_in[1];
    const float* V  = (const float*)d_in[2];
    const int*   BI = (const int*)d_in[3];
    pack_kernel<<<64, 256>>>(K, V);
    nsa9<<<TT, 64>>>(Q, BI, (float*)d_out);
}

// round 10
// speedup vs baseline: 15.4855x; 1.2473x over previous
#include <cuda_runtime.h>
#include <cuda_fp16.h>
#include <math.h>

#define TT 2048

// Fragment-ordered plain-fp16 K and V(transposed):
// [blk][nt][p][lane] -> int4 {b0(2p),b1(2p),b0(2p+1),b1(2p+1)} (fp16x2 each)
__device__ int4 g_K[32 * 8 * 2 * 32];   // 256 KB
__device__ int4 g_V[32 * 8 * 2 * 32];   // 256 KB

__device__ __forceinline__ unsigned h2u(float x, float y) {
    __half2 h = __floats2half2_rn(x, y);
    return *(unsigned*)&h;
}

__global__ void __launch_bounds__(256) pack_kernel(
    const float* __restrict__ K, const float* __restrict__ V)
{
    const int i    = blockIdx.x * 256 + threadIdx.x;   // 0..16383
    const int lane = i & 31;
    const int p    = (i >> 5) & 1;
    const int nt   = (i >> 6) & 7;
    const int blk  = i >> 9;
    const int gid  = lane >> 2, qid = lane & 3;
    const int r    = 8 * nt + gid;
    const int c0   = 32 * p + 2 * qid;
    const int c1   = c0 + 16;

    const float* Kb = K + blk * 4096;
    const float* Vb = V + blk * 4096;

    g_K[i] = make_int4(
        (int)h2u(Kb[r * 64 + c0],      Kb[r * 64 + c0 + 1]),
        (int)h2u(Kb[r * 64 + c0 + 8],  Kb[r * 64 + c0 + 9]),
        (int)h2u(Kb[r * 64 + c1],      Kb[r * 64 + c1 + 1]),
        (int)h2u(Kb[r * 64 + c1 + 8],  Kb[r * 64 + c1 + 9]));

    g_V[i] = make_int4(
        (int)h2u(Vb[c0 * 64 + r],       Vb[(c0 + 1) * 64 + r]),
        (int)h2u(Vb[(c0 + 8) * 64 + r], Vb[(c0 + 9) * 64 + r]),
        (int)h2u(Vb[c1 * 64 + r],       Vb[(c1 + 1) * 64 + r]),
        (int)h2u(Vb[(c1 + 8) * 64 + r], Vb[(c1 + 9) * 64 + r]));
}

__device__ __forceinline__ void mma16(float c[4], const int4 a, int b0, int b1) {
    asm volatile(
        "mma.sync.aligned.m16n8k16.row.col.f32.f16.f16.f32 "
        "{%0,%1,%2,%3}, {%4,%5,%6,%7}, {%8,%9}, {%0,%1,%2,%3};\n"
        : "+f"(c[0]), "+f"(c[1]), "+f"(c[2]), "+f"(c[3])
        : "r"(a.x), "r"(a.y), "r"(a.z), "r"(a.w), "r"(b0), "r"(b1));
}

__device__ __forceinline__ void cp16(int4* smem_dst, const int4* gmem_src) {
    unsigned sa = (unsigned)__cvta_generic_to_shared(smem_dst);
    asm volatile("cp.async.cg.shared.global [%0], [%1], 16;\n"
                 :: "r"(sa), "l"(gmem_src));
}
#define CP_COMMIT() asm volatile("cp.async.commit_group;\n" ::: "memory")
#define CP_WAIT2()  asm volatile("cp.async.wait_group 2;\n" ::: "memory")

#define ONES 0x3C003C00   // fp16x2 (1.0, 1.0)

__device__ __forceinline__ int p3(int x) { return (x >= 3) ? x - 3 : x; }

// Two warps per token (split-KV). NEW in R10: each warp compacts its 8 block
// indices to the causally-valid subset (blk*64 <= t) and runs only those —
// fully-masked blocks contribute exactly zero and are skipped (~48% of all
// blocks). Per-element masking is applied only for the one boundary block
// (blk == t>>6), via a warp-uniform branch. Everything else is R9: cp.async
// 3-slot K ring (2 halves ahead), early V LDGs, lazy-ref softmax, l via
// ones-MMA, split-softmax merge.
__global__ void __launch_bounds__(64, 8) nsa10(
    const float* __restrict__ Q,   // [T,16,64]
    const int*   __restrict__ BI,  // [T,16]
    float* __restrict__ Out)       // [T,16,64]
{
    __shared__ int4  sK[2 * 3 * 256];    // 2 warps x 3 slots x 4KB
    __shared__ float sm_m[2][16];
    __shared__ float sm_l[2][16];
    __shared__ float sm_o[16 * 66];
    #define KSLOT(wi, si, ei) sK[(wi) * 768 + (si) * 256 + (ei)]

    const int t    = blockIdx.x;
    const int w    = threadIdx.x >> 5;
    const int lane = threadIdx.x & 31;
    const int gid  = lane >> 2;
    const int qid  = lane & 3;
    const int pb   = t >> 6;             // the (only possible) partial block

    // ---- Q A-fragments (scaled by 0.125*log2e), plain fp16, in regs -------
    int4 Qh[4];
    {
        const float SC = 0.18033688011112042f;   // 0.125 * log2(e)
        const float* Qp = Q + t * 1024;
        #pragma unroll
        for (int ks = 0; ks < 4; ++ks) {
            const int c0 = 16 * ks + 2 * qid;
            float2 x0 = *(const float2*)(Qp + gid * 64 + c0);
            float2 x1 = *(const float2*)(Qp + (gid + 8) * 64 + c0);
            float2 x2 = *(const float2*)(Qp + gid * 64 + c0 + 8);
            float2 x3 = *(const float2*)(Qp + (gid + 8) * 64 + c0 + 8);
            Qh[ks] = make_int4(
                (int)h2u(x0.x * SC, x0.y * SC),
                (int)h2u(x1.x * SC, x1.y * SC),
                (int)h2u(x2.x * SC, x2.y * SC),
                (int)h2u(x3.x * SC, x3.y * SC));
        }
    }

    float o[8][4];
    #pragma unroll
    for (int dt = 0; dt < 8; ++dt)
        o[dt][0] = o[dt][1] = o[dt][2] = o[dt][3] = 0.f;
    float la[4] = {0.f, 0.f, 0.f, 0.f};
    float m0 = -INFINITY, m1 = -INFINITY;
    float ref0 = 0.f, ref1 = 0.f;

    // ---- compact causally-valid block list --------------------------------
    const int* bip = BI + t * 16 + w * 8;
    int lst[8];
    int cnt = 0;
    #pragma unroll
    for (int s = 0; s < 8; ++s) {
        const int b = __ldg(bip + s);
        if (b <= pb) lst[cnt++] = b;     // b*64 <= t  <=>  b <= t>>6
    }

    if (cnt > 0) {
        // ---- preload: (lst0, half0) -> slot0, (lst0, half1) -> slot1 ------
        {
            const int4* srcb = g_K + (size_t)lst[0] * 512;
            #pragma unroll
            for (int j = 0; j < 8; ++j)
                cp16(&KSLOT(w, 0, j * 32 + lane), srcb + j * 32 + lane);
            CP_COMMIT();
            #pragma unroll
            for (int j = 0; j < 8; ++j)
                cp16(&KSLOT(w, 1, j * 32 + lane), srcb + 256 + j * 32 + lane);
            CP_COMMIT();
        }

        int cslot = 0;

        #pragma unroll 1
        for (int i = 0; i < cnt; ++i) {
            const int blkc = lst[i];
            const int nxt  = (i + 1 < cnt) ? lst[i + 1] : 0;
            const bool domask = (blkc == pb);
            const int4* Vb = g_V + (size_t)blkc * 512;
            const int4* Kn = g_K + (size_t)nxt * 512;

            float bm0 = m0, bm1 = m1;
            int4 Ph[2];

            #pragma unroll
            for (int h = 0; h < 2; ++h) {
                // -- issue next block's same-half K into slot cslot+2 -------
                {
                    const int4* src = Kn + h * 256;
                    const int tslot = p3(cslot + 2);
                    #pragma unroll
                    for (int j = 0; j < 8; ++j)
                        cp16(&KSLOT(w, tslot, j * 32 + lane), src + j * 32 + lane);
                    CP_COMMIT();
                }
                // -- early V loads for this half ----------------------------
                int4 v[8];
                #pragma unroll
                for (int dt = 0; dt < 8; ++dt)
                    v[dt] = Vb[dt * 64 + 32 * h + lane];

                // -- wait for this half's K, then QK ------------------------
                CP_WAIT2();
                float sc[4][4];
                #pragma unroll
                for (int nt = 0; nt < 4; ++nt) {
                    const int4 ba = KSLOT(w, cslot, nt * 64 + lane);
                    const int4 bb = KSLOT(w, cslot, nt * 64 + 32 + lane);
                    float a[4] = {0.f, 0.f, 0.f, 0.f};
                    mma16(a, Qh[0], ba.x, ba.y);
                    mma16(a, Qh[1], ba.z, ba.w);
                    mma16(a, Qh[2], bb.x, bb.y);
                    mma16(a, Qh[3], bb.z, bb.w);
                    sc[nt][0] = a[0]; sc[nt][1] = a[1];
                    sc[nt][2] = a[2]; sc[nt][3] = a[3];
                }
                if (domask) {   // warp-uniform: only the boundary block
                    #pragma unroll
                    for (int nt = 0; nt < 4; ++nt) {
                        const int kp = blkc * 64 + 8 * (nt + 4 * h) + 2 * qid;
                        if (kp     > t) { sc[nt][0] = -INFINITY; sc[nt][2] = -INFINITY; }
                        if (kp + 1 > t) { sc[nt][1] = -INFINITY; sc[nt][3] = -INFINITY; }
                    }
                }
                #pragma unroll
                for (int nt = 0; nt < 4; ++nt) {
                    bm0 = fmaxf(bm0, fmaxf(sc[nt][0], sc[nt][1]));
                    bm1 = fmaxf(bm1, fmaxf(sc[nt][2], sc[nt][3]));
                }
                // -- exp (lazy reference) -> P A-fragments ------------------
                #pragma unroll
                for (int p = 0; p < 2; ++p) {
                    unsigned hb[4];
                    #pragma unroll
                    for (int j = 0; j < 2; ++j) {
                        const int nt = 2 * p + j;
                        __half2 e01 = h2exp2(__floats2half2_rn(sc[nt][0] - ref0,
                                                               sc[nt][1] - ref0));
                        __half2 e23 = h2exp2(__floats2half2_rn(sc[nt][2] - ref1,
                                                               sc[nt][3] - ref1));
                        hb[2 * j]     = *(unsigned*)&e01;
                        hb[2 * j + 1] = *(unsigned*)&e23;
                    }
                    Ph[p] = make_int4((int)hb[0], (int)hb[1], (int)hb[2], (int)hb[3]);
                }
                // -- PV over this half's k-steps ----------------------------
                #pragma unroll
                for (int dt = 0; dt < 8; ++dt) {
                    mma16(o[dt], Ph[0], v[dt].x, v[dt].y);
                    mma16(o[dt], Ph[1], v[dt].z, v[dt].w);
                }
                mma16(la, Ph[0], ONES, ONES);
                mma16(la, Ph[1], ONES, ONES);

                cslot = p3(cslot + 1);
            }

            // ---- block end: update max / reference, rescale ---------------
            bm0 = fmaxf(bm0, __shfl_xor_sync(0xffffffffu, bm0, 1));
            bm0 = fmaxf(bm0, __shfl_xor_sync(0xffffffffu, bm0, 2));
            bm1 = fmaxf(bm1, __shfl_xor_sync(0xffffffffu, bm1, 1));
            bm1 = fmaxf(bm1, __shfl_xor_sync(0xffffffffu, bm1, 2));
            const float nr0 = (bm0 == -INFINITY) ? 0.f : bm0;
            const float nr1 = (bm1 == -INFINITY) ? 0.f : bm1;
            const float cr0 = exp2f(ref0 - nr0);
            const float cr1 = exp2f(ref1 - nr1);
            #pragma unroll
            for (int dt = 0; dt < 8; ++dt) {
                o[dt][0] *= cr0; o[dt][1] *= cr0;
                o[dt][2] *= cr1; o[dt][3] *= cr1;
            }
            la[0] *= cr0; la[1] *= cr0; la[2] *= cr1; la[3] *= cr1;
            m0 = bm0; m1 = bm1; ref0 = nr0; ref1 = nr1;
        }
    }

    // ---- split-softmax merge ----------------------------------------------
    if (qid == 0) {
        sm_m[w][gid] = m0;  sm_m[w][gid + 8] = m1;
        sm_l[w][gid] = la[0]; sm_l[w][gid + 8] = la[2];
    }
    __syncthreads();

    const float M0 = fmaxf(sm_m[0][gid],     sm_m[1][gid]);   // finite (w0 has blk 0)
    const float M1 = fmaxf(sm_m[0][gid + 8], sm_m[1][gid + 8]);
    const float a0 = exp2f(ref0 - M0);
    const float a1 = exp2f(ref1 - M1);

    if (w == 0) {
        #pragma unroll
        for (int dt = 0; dt < 8; ++dt) {
            *(float2*)(sm_o + gid * 66 + 8 * dt + 2 * qid) =
                make_float2(o[dt][0] * a0, o[dt][1] * a0);
            *(float2*)(sm_o + (gid + 8) * 66 + 8 * dt + 2 * qid) =
                make_float2(o[dt][2] * a1, o[dt][3] * a1);
        }
    }
    __syncthreads();
    if (w == 1) {
        const float rf00 = (sm_m[0][gid] == -INFINITY)     ? 0.f : sm_m[0][gid];
        const float rf10 = (sm_m[1][gid] == -INFINITY)     ? 0.f : sm_m[1][gid];
        const float rf01 = (sm_m[0][gid + 8] == -INFINITY) ? 0.f : sm_m[0][gid + 8];
        const float rf11 = (sm_m[1][gid + 8] == -INFINITY) ? 0.f : sm_m[1][gid + 8];
        const float L0 = exp2f(rf00 - M0) * sm_l[0][gid]
                       + exp2f(rf10 - M0) * sm_l[1][gid];
        const float L1 = exp2f(rf01 - M1) * sm_l[0][gid + 8]
                       + exp2f(rf11 - M1) * sm_l[1][gid + 8];
        const float i0 = 1.f / L0;
        const float i1 = 1.f / L1;
        float* ob = Out + t * 1024;
        #pragma unroll
        for (int dt = 0; dt < 8; ++dt) {
            float2 u0 = *(float2*)(sm_o + gid * 66 + 8 * dt + 2 * qid);
            float2 u1 = *(float2*)(sm_o + (gid + 8) * 66 + 8 * dt + 2 * qid);
            *(float2*)(ob + gid * 64 + 8 * dt + 2 * qid) =
                make_float2((u0.x + o[dt][0] * a0) * i0,
                            (u0.y + o[dt][1] * a0) * i0);
            *(float2*)(ob + (gid + 8) * 64 + 8 * dt + 2 * qid) =
                make_float2((u1.x + o[dt][2] * a1) * i1,
                            (u1.y + o[dt][3] * a1) * i1);
        }
    }
}

extern "C" void kernel_launch(void* const* d_in, const int* in_sizes, int n_in,
                              void* d_out, int out_size) {
    const float* Q  = (const float*)d_in[0];
    const float* K  = (const float*)d_in[1];
    const float* V  = (const float*)d_in[2];
    const int*   BI = (const int*)d_in[3];
    pack_kernel<<<64, 256>>>(K, V);
    nsa10<<<TT, 64>>>(Q, BI, (float*)d_out);
}